// round 11
// baseline (speedup 1.0000x reference)
#include <cuda_runtime.h>
#include <cuda_fp16.h>
#include <cstdint>

// Problem constants
#define BB 2
#define HH 56
#define WW 56
#define CC 256
#define HEADS 8
#define NPIX (BB*HH*WW)          // 6272
#define KV_N 512
#define RPB_S 13
#define K2 512                   // 2 * CC (split-fp16 K dimension)

typedef __half h16;

// Scratch (no cudaMalloc allowed)
__device__ h16 g_kv  [NPIX * KV_N];   // fp16: key c[0:256], val c[256:512]
__device__ h16 g_x2  [NPIX * K2];     // [xh, xl]
__device__ h16 g_att2[NPIX * K2];     // [ah, al]
__device__ h16 g_w2  [KV_N * K2];     // [wh, wh]
__device__ h16 g_pw2 [CC   * K2];     // [wh, wh]

// ---------------------------------------------------------------------------
// PTX helpers (scalar args only)
// ---------------------------------------------------------------------------
__device__ __forceinline__ void cp_async16(unsigned dst, const void* src)
{
    asm volatile("cp.async.cg.shared.global [%0], [%1], 16;"
                 :: "r"(dst), "l"(src));
}
__device__ __forceinline__ void cp_commit()
{
    asm volatile("cp.async.commit_group;");
}
__device__ __forceinline__ void cp_wait2()
{
    asm volatile("cp.async.wait_group 2;");
}
__device__ __forceinline__ void cp_wait0()
{
    asm volatile("cp.async.wait_group 0;");
}
__device__ __forceinline__ void ldmx4(uint32_t& r0, uint32_t& r1,
                                      uint32_t& r2, uint32_t& r3, unsigned addr)
{
    asm volatile("ldmatrix.sync.aligned.m8n8.x4.shared.b16 {%0,%1,%2,%3}, [%4];"
                 : "=r"(r0), "=r"(r1), "=r"(r2), "=r"(r3) : "r"(addr));
}
__device__ __forceinline__ void mma16816(float& d0, float& d1, float& d2, float& d3,
                                         uint32_t a0, uint32_t a1, uint32_t a2, uint32_t a3,
                                         uint32_t b0, uint32_t b1)
{
    asm volatile("mma.sync.aligned.m16n8k16.row.col.f32.f16.f16.f32 "
                 "{%0,%1,%2,%3}, {%4,%5,%6,%7}, {%8,%9}, {%0,%1,%2,%3};"
                 : "+f"(d0), "+f"(d1), "+f"(d2), "+f"(d3)
                 : "r"(a0), "r"(a1), "r"(a2), "r"(a3), "r"(b0), "r"(b1));
}

// ---------------------------------------------------------------------------
// fused split: fp32 [rows][256] -> fp16 [rows][512] for x, kv_w, proj_w.
// ---------------------------------------------------------------------------
#define NX (NPIX * CC)
#define NW (KV_N * CC)
#define NPW (CC * CC)
#define NSPLIT (NX + NW + NPW)

__global__ void split_all_kernel(const float* __restrict__ x,
                                 const float* __restrict__ kv_w,
                                 const float* __restrict__ proj_w,
                                 h16* __restrict__ x2,
                                 h16* __restrict__ w2,
                                 h16* __restrict__ pw2)
{
    int idx = blockIdx.x * 256 + threadIdx.x;
    if (idx >= NSPLIT) return;

    const float* src;
    h16* dst;
    int actside;
    if (idx < NX)            { src = x;      dst = x2;  actside = 1; }
    else if (idx < NX + NW)  { idx -= NX;  src = kv_w;   dst = w2;  actside = 0; }
    else                     { idx -= NX + NW; src = proj_w; dst = pw2; actside = 0; }

    int row = idx >> 8, col = idx & 255;
    float v = src[idx];
    h16 hi = __float2half_rn(v);
    h16* dp = dst + (size_t)row * K2 + col;
    dp[0]   = hi;
    dp[256] = actside ? __float2half_rn(v - __half2float(hi)) : hi;
}

// ---------------------------------------------------------------------------
// fp16 tensor-core GEMM: C[M,N] = A2[M,512] @ B2[N,512]^T + bias
// OUTH=1 -> h16 output, OUTH=0 -> fp32 output.
// ---------------------------------------------------------------------------
template<int BN, int OUTH>
__global__ void __launch_bounds__(256, 2)
gemm_f16(const h16* __restrict__ Amat, const h16* __restrict__ Bmat,
         const float* __restrict__ bias, void* __restrict__ Cmat,
         int Mdim, int Ndim)
{
    constexpr int NT = BN / 32;
    constexpr int NP = BN / 64;
    constexpr unsigned STAGE = (128 + BN) * 80;

    extern __shared__ __align__(16) char smraw[];
    const unsigned smem0 = (unsigned)__cvta_generic_to_shared(smraw);

    const int tid  = threadIdx.x;
    const int lane = tid & 31;
    const int wrp  = tid >> 5;
    const int wm   = wrp & 1;
    const int wn   = wrp >> 1;
    const int m0   = blockIdx.y * 128;
    const int n0   = blockIdx.x * BN;

    const int rr = tid >> 2;
    const int qq = tid & 3;
    const h16* gA0 = Amat + (size_t)(m0 + rr) * K2 + qq * 8;
    const h16* gA1 = gA0 + (size_t)64 * K2;
    const h16* gB0 = Bmat + (size_t)(n0 + rr) * K2 + qq * 8;
    const h16* gB1 = gB0 + (size_t)64 * K2;
    const unsigned sA0 = smem0 + rr * 80 + qq * 16;
    const unsigned sA1 = sA0 + 5120;
    const unsigned sB0 = sA0 + 10240;
    const unsigned sB1 = sB0 + 5120;

    const unsigned almb = smem0 +
        (unsigned)((wm * 64 + (lane & 15)) * 80 + (lane >> 4) * 16);
    const unsigned blmb = smem0 + 10240u +
        (unsigned)((wn * (BN / 4) + (lane & 7) + ((lane >> 4) << 3)) * 80
                   + ((lane >> 3) & 1) * 16);

    float acc[4][NT][4];
#pragma unroll
    for (int mt = 0; mt < 4; mt++)
#pragma unroll
        for (int nt = 0; nt < NT; nt++)
#pragma unroll
            for (int e = 0; e < 4; e++) acc[mt][nt][e] = 0.0f;

#pragma unroll
    for (int st = 0; st < 3; st++) {
        unsigned off = (unsigned)st * STAGE;
        cp_async16(sA0 + off, gA0 + st * 32);
        cp_async16(sA1 + off, gA1 + st * 32);
        cp_async16(sB0 + off, gB0 + st * 32);
        if (BN == 128) cp_async16(sB1 + off, gB1 + st * 32);
        cp_commit();
    }

    const int T = K2 / 32;
    for (int t = 0; t < T; t++) {
        if (t < T - 2) cp_wait2();
        else           cp_wait0();
        __syncthreads();

        if (t + 3 < T) {
            const unsigned off = (unsigned)((t + 3) & 3) * STAGE;
            const int kt = t + 3;
            cp_async16(sA0 + off, gA0 + kt * 32);
            cp_async16(sA1 + off, gA1 + kt * 32);
            cp_async16(sB0 + off, gB0 + kt * 32);
            if (BN == 128) cp_async16(sB1 + off, gB1 + kt * 32);
            cp_commit();
        }

        const unsigned so = (unsigned)(t & 3) * STAGE;
#pragma unroll
        for (int ks = 0; ks < 2; ks++) {
            uint32_t afr[4][4];
            uint32_t bfr[NP][4];
#pragma unroll
            for (int mt = 0; mt < 4; mt++)
                ldmx4(afr[mt][0], afr[mt][1], afr[mt][2], afr[mt][3],
                      almb + so + mt * 1280 + ks * 32);
#pragma unroll
            for (int np = 0; np < NP; np++)
                ldmx4(bfr[np][0], bfr[np][1], bfr[np][2], bfr[np][3],
                      blmb + so + np * 1280 + ks * 32);
#pragma unroll
            for (int mt = 0; mt < 4; mt++) {
#pragma unroll
                for (int nt = 0; nt < NT; nt++) {
                    mma16816(acc[mt][nt][0], acc[mt][nt][1],
                             acc[mt][nt][2], acc[mt][nt][3],
                             afr[mt][0], afr[mt][1], afr[mt][2], afr[mt][3],
                             bfr[nt >> 1][(nt & 1) * 2],
                             bfr[nt >> 1][(nt & 1) * 2 + 1]);
                }
            }
        }
    }

    float2 bv[NT];
#pragma unroll
    for (int nt = 0; nt < NT; nt++)
        bv[nt] = *(const float2*)&bias[n0 + wn * (BN / 4) + nt * 8 + (lane & 3) * 2];

#pragma unroll
    for (int mt = 0; mt < 4; mt++) {
        const int row = m0 + wm * 64 + mt * 16 + (lane >> 2);
#pragma unroll
        for (int nt = 0; nt < NT; nt++) {
            const int col = n0 + wn * (BN / 4) + nt * 8 + (lane & 3) * 2;
            float v00 = acc[mt][nt][0] + bv[nt].x;
            float v01 = acc[mt][nt][1] + bv[nt].y;
            float v10 = acc[mt][nt][2] + bv[nt].x;
            float v11 = acc[mt][nt][3] + bv[nt].y;
            if (OUTH) {
                h16* Cm = (h16*)Cmat;
                *(half2*)&Cm[(size_t)row * Ndim + col]       = __floats2half2_rn(v00, v01);
                *(half2*)&Cm[(size_t)(row + 8) * Ndim + col] = __floats2half2_rn(v10, v11);
            } else {
                float* Cf = (float*)Cmat;
                *(float2*)&Cf[(size_t)row * Ndim + col]       = make_float2(v00, v01);
                *(float2*)&Cf[(size_t)(row + 8) * Ndim + col] = make_float2(v10, v11);
            }
        }
    }
}

// ---------------------------------------------------------------------------
// Tensor-core neighborhood attention (fully static warp schedule).
// Block = (8x8 pixel tile, head, batch). 64 tasks share a 14x14 window.
// Columns padded 196 -> 256 (16 k16-tiles); warp w owns tiles {w, w+8}.
//   S[64x256] = Q[64x32] @ K[256x32]^T   (K rows 196-255 zeroed)
//   P = exp(S + bias) masked per task's 7x7 window (no max shift)
//   O[64x48] = P[64x256] @ Vt[48x256]^T  (Vt row 32 = ones -> col 32 = z)
//   out = O / z, stored as split-fp16 [hi, lo].
// ---------------------------------------------------------------------------
#define SM_Q  0        // 64 x 80B     = 5120
#define SM_K  5120     // 256 x 80B    = 20480
#define SM_VT 25600    // 48 x 528B    = 25344
#define SM_P  50944    // 64 x 528B    = 33792
#define SM_RS 84736    // 169 x 4B
#define SM_ZS 85416    // 64 x 4B
#define NATT_SMEM 85760

__device__ __forceinline__ float nat_score(float s, int row, int col,
                                           int i0, int j0, int u0, int v0,
                                           const float* rs)
{
    const int trow = row >> 3, tj = row & 7;
    const int i = i0 + trow, j = j0 + tj;
    const int ar  = min(max(i - 3, 0), HH - 7) - u0;
    const int pis = 3 + max(3 - i, 0) + min(HH - 4 - i, 0);
    const int jc  = min(max(j - 3, 0), WW - 7) - v0;
    const int pjs = 3 + max(3 - j, 0) + min(WW - 4 - j, 0);
    const int wr = (col * 4682) >> 16;       // col / 14 for col < 500
    const int wc = col - wr * 14;
    const int uu = wr - ar;
    const int vv = wc - jc;
    if ((unsigned)uu < 7u && (unsigned)vv < 7u)
        return __expf(s + rs[(pis + uu) * RPB_S + pjs + vv]);
    return 0.0f;
}

__global__ void __launch_bounds__(256, 2)
natt_mma_kernel(const float* __restrict__ q_extra,
                const float* __restrict__ rpb)
{
    extern __shared__ __align__(16) char smraw[];
    const unsigned sm0 = (unsigned)__cvta_generic_to_shared(smraw);
    float* rs = (float*)(smraw + SM_RS);

    const int tid  = threadIdx.x;
    const int lane = tid & 31;
    const int w    = tid >> 5;
    const int bb   = blockIdx.z;
    const int h    = blockIdx.y;
    const int i0   = (blockIdx.x / 7) * 8;
    const int j0   = (blockIdx.x % 7) * 8;
    const int u0   = min(max(i0 - 3, 0), HH - 14);
    const int v0   = min(max(j0 - 3, 0), WW - 14);
    const float scale = 0.17677669529663687f;

    // ---- stage phase ----
    for (int idx = tid; idx < RPB_S * RPB_S; idx += 256)
        rs[idx] = rpb[h * RPB_S * RPB_S + idx];

    // zero K pad rows 196-255 (60 rows x 5 uint4)
    for (int idx = tid; idx < 300; idx += 256)
        *(uint4*)(smraw + SM_K + (196 + idx / 5) * 80 + (idx % 5) * 16) =
            make_uint4(0, 0, 0, 0);
    // zero all of Vt (48 rows x 33 uint4)
    for (int idx = tid; idx < 48 * 33; idx += 256)
        *(uint4*)(smraw + SM_VT + (idx / 33) * 528 + (idx % 33) * 16) =
            make_uint4(0, 0, 0, 0);

    // Q: 64 tasks x 32 dims fp32 -> fp16 * scale
    for (int idx = tid; idx < 512; idx += 256) {
        int task = idx >> 3, c4 = idx & 7;
        int ii = i0 + (task >> 3), jj = j0 + (task & 7);
        int pix = (bb * HH + ii) * WW + jj;
        float4 v = *(const float4*)&q_extra[(size_t)pix * CC + h * 32 + c4 * 4];
        half2* dq = (half2*)(smraw + SM_Q + task * 80 + c4 * 8);
        dq[0] = __floats2half2_rn(v.x * scale, v.y * scale);
        dq[1] = __floats2half2_rn(v.z * scale, v.w * scale);
    }

    // K: 196 window pixels x 32 h16 (4 x 16B each)
    for (int idx = tid; idx < 196 * 4; idx += 256) {
        int wp = idx >> 2, c = idx & 3;
        int wr = wp / 14, wc = wp % 14;
        int pix = (bb * HH + u0 + wr) * WW + v0 + wc;
        uint4 val = *(const uint4*)(g_kv + (size_t)pix * KV_N + h * 32 + c * 8);
        *(uint4*)(smraw + SM_K + wp * 80 + c * 16) = val;
    }
    __syncthreads();   // Vt zero must complete before transpose fill

    // Vt: transpose V window into [dim][wp] (stride 528B)
    for (int idx = tid; idx < 196 * 32; idx += 256) {
        int wp = idx >> 5, d = idx & 31;
        int wr = wp / 14, wc = wp % 14;
        int pix = (bb * HH + u0 + wr) * WW + v0 + wc;
        h16 v = g_kv[(size_t)pix * KV_N + 256 + h * 32 + d];
        *(h16*)(smraw + SM_VT + d * 528 + wp * 2) = v;
    }
    // ones row (dim 32) for z over the 196 real columns
    for (int idx = tid; idx < 196; idx += 256)
        *(h16*)(smraw + SM_VT + 32 * 528 + idx * 2) = __float2half_rn(1.0f);

    __syncthreads();

    // ---- QK phase: warp w owns column tiles {w, w+8}; fully static ----
    uint32_t afr[4][2][4];
#pragma unroll
    for (int mt = 0; mt < 4; mt++)
#pragma unroll
        for (int ks = 0; ks < 2; ks++)
            ldmx4(afr[mt][ks][0], afr[mt][ks][1], afr[mt][ks][2], afr[mt][ks][3],
                  sm0 + SM_Q + (mt * 16 + (lane & 15)) * 80 + (lane >> 4) * 16 + ks * 32);

#pragma unroll
    for (int pi = 0; pi < 2; pi++) {
        const int p = w + pi * 8;          // column k16-tile index (0..15)
        float qc0[4][4], qc1[4][4];
#pragma unroll
        for (int mt = 0; mt < 4; mt++)
#pragma unroll
            for (int e = 0; e < 4; e++) { qc0[mt][e] = 0.0f; qc1[mt][e] = 0.0f; }

#pragma unroll
        for (int ks = 0; ks < 2; ks++) {
            uint32_t bf[4];
            ldmx4(bf[0], bf[1], bf[2], bf[3],
                  sm0 + SM_K + (p * 16 + (lane & 7) + ((lane >> 4) << 3)) * 80
                  + ((lane >> 3) & 1) * 16 + ks * 32);
#pragma unroll
            for (int mt = 0; mt < 4; mt++) {
                mma16816(qc0[mt][0], qc0[mt][1], qc0[mt][2], qc0[mt][3],
                         afr[mt][ks][0], afr[mt][ks][1], afr[mt][ks][2], afr[mt][ks][3],
                         bf[0], bf[1]);
                mma16816(qc1[mt][0], qc1[mt][1], qc1[mt][2], qc1[mt][3],
                         afr[mt][ks][0], afr[mt][ks][1], afr[mt][ks][2], afr[mt][ks][3],
                         bf[2], bf[3]);
            }
        }

        // bias + mask + exp -> P (fp16, unnormalized); covers cols p*16..p*16+15
        const int cq = (lane & 3) * 2;
#pragma unroll
        for (int mt = 0; mt < 4; mt++) {
            const int r0 = mt * 16 + (lane >> 2);
            {
                const int c0 = p * 16 + cq;
                float v00 = nat_score(qc0[mt][0], r0,     c0,     i0, j0, u0, v0, rs);
                float v01 = nat_score(qc0[mt][1], r0,     c0 + 1, i0, j0, u0, v0, rs);
                float v10 = nat_score(qc0[mt][2], r0 + 8, c0,     i0, j0, u0, v0, rs);
                float v11 = nat_score(qc0[mt][3], r0 + 8, c0 + 1, i0, j0, u0, v0, rs);
                *(half2*)(smraw + SM_P + r0 * 528 + c0 * 2)       = __floats2half2_rn(v00, v01);
                *(half2*)(smraw + SM_P + (r0 + 8) * 528 + c0 * 2) = __floats2half2_rn(v10, v11);
            }
            {
                const int c0 = p * 16 + 8 + cq;
                float v00 = nat_score(qc1[mt][0], r0,     c0,     i0, j0, u0, v0, rs);
                float v01 = nat_score(qc1[mt][1], r0,     c0 + 1, i0, j0, u0, v0, rs);
                float v10 = nat_score(qc1[mt][2], r0 + 8, c0,     i0, j0, u0, v0, rs);
                float v11 = nat_score(qc1[mt][3], r0 + 8, c0 + 1, i0, j0, u0, v0, rs);
                *(half2*)(smraw + SM_P + r0 * 528 + c0 * 2)       = __floats2half2_rn(v00, v01);
                *(half2*)(smraw + SM_P + (r0 + 8) * 528 + c0 * 2) = __floats2half2_rn(v10, v11);
            }
        }
    }

    __syncthreads();

    // ---- AV phase: O[64x48] = P[64x256] @ Vt[48x256]^T ----
    const int  mtav    = w & 3;
    const bool hi_half = (w >= 4);
    float av[3][4];
#pragma unroll
    for (int u2 = 0; u2 < 3; u2++)
#pragma unroll
        for (int e = 0; e < 4; e++) av[u2][e] = 0.0f;

    const unsigned pa = sm0 + SM_P +
        (mtav * 16 + (lane & 15)) * 528 + (lane >> 4) * 16;
    const unsigned pb = sm0 + SM_VT +
        ((hi_half ? 16 : 0) + (lane & 7) + ((lane >> 4) << 3)) * 528
        + ((lane >> 3) & 1) * 16;
    const unsigned pb2 = sm0 + SM_VT +
        (32 + (lane & 7) + ((lane >> 4) << 3)) * 528 + ((lane >> 3) & 1) * 16;

#pragma unroll
    for (int ks = 0; ks < 16; ks++) {
        uint32_t a4[4], b4[4];
        ldmx4(a4[0], a4[1], a4[2], a4[3], pa + ks * 32);
        ldmx4(b4[0], b4[1], b4[2], b4[3], pb + ks * 32);
        mma16816(av[0][0], av[0][1], av[0][2], av[0][3],
                 a4[0], a4[1], a4[2], a4[3], b4[0], b4[1]);
        mma16816(av[1][0], av[1][1], av[1][2], av[1][3],
                 a4[0], a4[1], a4[2], a4[3], b4[2], b4[3]);
        if (hi_half) {
            uint32_t b2[4];
            ldmx4(b2[0], b2[1], b2[2], b2[3], pb2 + ks * 32);
            mma16816(av[2][0], av[2][1], av[2][2], av[2][3],
                     a4[0], a4[1], a4[2], a4[3], b2[0], b2[1]);
        }
    }

    // z (col 32) -> smem
    if (hi_half && (lane & 3) == 0) {
        const int r0 = mtav * 16 + (lane >> 2);
        *(float*)(smraw + SM_ZS + r0 * 4)       = av[2][0];
        *(float*)(smraw + SM_ZS + (r0 + 8) * 4) = av[2][2];
    }
    __syncthreads();

    // ---- normalize + store split-fp16 ----
    {
        const int r0 = mtav * 16 + (lane >> 2);
        const float zi0 = __frcp_rn(*(float*)(smraw + SM_ZS + r0 * 4));
        const float zi1 = __frcp_rn(*(float*)(smraw + SM_ZS + (r0 + 8) * 4));
        const int pix0 = (bb * HH + i0 + (r0 >> 3)) * WW + j0 + (r0 & 7);
        const int pix1 = (bb * HH + i0 + (r0 >> 3) + 1) * WW + j0 + (r0 & 7);
#pragma unroll
        for (int nti = 0; nti < 2; nti++) {
            const int d0 = (hi_half ? 16 : 0) + nti * 8 + (lane & 3) * 2;
            float o00 = av[nti][0] * zi0, o01 = av[nti][1] * zi0;
            float o10 = av[nti][2] * zi1, o11 = av[nti][3] * zi1;

            h16* dst0 = g_att2 + (size_t)pix0 * K2 + h * 32 + d0;
            half2 h0 = __floats2half2_rn(o00, o01);
            *(half2*)dst0 = h0;
            float2 f0 = __half22float2(h0);
            *(half2*)(dst0 + 256) = __floats2half2_rn(o00 - f0.x, o01 - f0.y);

            h16* dst1 = g_att2 + (size_t)pix1 * K2 + h * 32 + d0;
            half2 h1 = __floats2half2_rn(o10, o11);
            *(half2*)dst1 = h1;
            float2 f1 = __half22float2(h1);
            *(half2*)(dst1 + 256) = __floats2half2_rn(o10 - f1.x, o11 - f1.y);
        }
    }
}

// ---------------------------------------------------------------------------
// Launch
// ---------------------------------------------------------------------------
extern "C" void kernel_launch(void* const* d_in, const int* in_sizes, int n_in,
                              void* d_out, int out_size)
{
    const float* x       = (const float*)d_in[0];
    const float* q_extra = (const float*)d_in[1];
    const float* kv_w    = (const float*)d_in[2];
    const float* kv_b    = (const float*)d_in[3];
    const float* rpb     = (const float*)d_in[4];
    const float* proj_w  = (const float*)d_in[5];
    const float* proj_b  = (const float*)d_in[6];
    float* out = (float*)d_out;

    h16 *kv_ptr = nullptr, *x2_ptr = nullptr, *att2_ptr = nullptr;
    h16 *w2_ptr = nullptr, *pw2_ptr = nullptr;
    cudaGetSymbolAddress((void**)&kv_ptr,   g_kv);
    cudaGetSymbolAddress((void**)&x2_ptr,   g_x2);
    cudaGetSymbolAddress((void**)&att2_ptr, g_att2);
    cudaGetSymbolAddress((void**)&w2_ptr,   g_w2);
    cudaGetSymbolAddress((void**)&pw2_ptr,  g_pw2);

    const int smem128 = 4 * (128 + 128) * 80;   // 81920
    const int smem64  = 4 * (128 + 64)  * 80;   // 61440
    cudaFuncSetAttribute(gemm_f16<128, 1>,
                         cudaFuncAttributeMaxDynamicSharedMemorySize, smem128);
    cudaFuncSetAttribute(gemm_f16<64, 0>,
                         cudaFuncAttributeMaxDynamicSharedMemorySize, smem64);
    cudaFuncSetAttribute(natt_mma_kernel,
                         cudaFuncAttributeMaxDynamicSharedMemorySize, NATT_SMEM);

    // 0) fused split: fp32 -> 2-term fp16 (x, kv_w, proj_w)
    split_all_kernel<<<(NSPLIT + 255) / 256, 256>>>(
        x, kv_w, proj_w, x2_ptr, w2_ptr, pw2_ptr);

    // 1) kv = x @ kv_w^T + kv_b   (fp16 output)
    gemm_f16<128, 1><<<dim3(KV_N / 128, NPIX / 128), 256, smem128>>>(
        x2_ptr, w2_ptr, kv_b, kv_ptr, NPIX, KV_N);

    // 2) tensor-core neighborhood attention: 8x8 tiles -> grid (49, 8, 2)
    natt_mma_kernel<<<dim3(49, HEADS, BB), 256, NATT_SMEM>>>(q_extra, rpb);

    // 3) out = att @ proj_w^T + proj_b   (fp32 output)
    gemm_f16<64, 0><<<dim3(CC / 64, NPIX / 128), 256, smem64>>>(
        att2_ptr, pw2_ptr, proj_b, out, NPIX, CC);
}

// round 12
// speedup vs baseline: 1.4839x; 1.4839x over previous
#include <cuda_runtime.h>
#include <cuda_fp16.h>
#include <cstdint>

// Problem constants
#define BB 2
#define HH 56
#define WW 56
#define CC 256
#define HEADS 8
#define NPIX (BB*HH*WW)          // 6272
#define KV_N 512
#define RPB_S 13
#define K2 512                   // 2 * CC (split-fp16 K dimension)

typedef __half h16;

// Scratch (no cudaMalloc allowed)
__device__ h16 g_kv  [NPIX * KV_N];   // fp16: key c[0:256], val c[256:512]
__device__ h16 g_x2  [NPIX * K2];     // [xh, xl]
__device__ h16 g_att2[NPIX * K2];     // [ah, al]
__device__ h16 g_w2  [KV_N * K2];     // [wh, wh]
__device__ h16 g_pw2 [CC   * K2];     // [wh, wh]

// ---------------------------------------------------------------------------
// PTX helpers (scalar args only)
// ---------------------------------------------------------------------------
__device__ __forceinline__ void cp_async16(unsigned dst, const void* src)
{
    asm volatile("cp.async.cg.shared.global [%0], [%1], 16;"
                 :: "r"(dst), "l"(src));
}
__device__ __forceinline__ void cp_commit()
{
    asm volatile("cp.async.commit_group;");
}
__device__ __forceinline__ void cp_wait2()
{
    asm volatile("cp.async.wait_group 2;");
}
__device__ __forceinline__ void cp_wait0()
{
    asm volatile("cp.async.wait_group 0;");
}
__device__ __forceinline__ void ldmx4(uint32_t& r0, uint32_t& r1,
                                      uint32_t& r2, uint32_t& r3, unsigned addr)
{
    asm volatile("ldmatrix.sync.aligned.m8n8.x4.shared.b16 {%0,%1,%2,%3}, [%4];"
                 : "=r"(r0), "=r"(r1), "=r"(r2), "=r"(r3) : "r"(addr));
}
__device__ __forceinline__ void mma16816(float& d0, float& d1, float& d2, float& d3,
                                         uint32_t a0, uint32_t a1, uint32_t a2, uint32_t a3,
                                         uint32_t b0, uint32_t b1)
{
    asm volatile("mma.sync.aligned.m16n8k16.row.col.f32.f16.f16.f32 "
                 "{%0,%1,%2,%3}, {%4,%5,%6,%7}, {%8,%9}, {%0,%1,%2,%3};"
                 : "+f"(d0), "+f"(d1), "+f"(d2), "+f"(d3)
                 : "r"(a0), "r"(a1), "r"(a2), "r"(a3), "r"(b0), "r"(b1));
}

// ---------------------------------------------------------------------------
// fused split: fp32 [rows][256] -> fp16 [rows][512] for x, kv_w, proj_w.
// ---------------------------------------------------------------------------
#define NX (NPIX * CC)
#define NW (KV_N * CC)
#define NPW (CC * CC)
#define NSPLIT (NX + NW + NPW)

__global__ void split_all_kernel(const float* __restrict__ x,
                                 const float* __restrict__ kv_w,
                                 const float* __restrict__ proj_w,
                                 h16* __restrict__ x2,
                                 h16* __restrict__ w2,
                                 h16* __restrict__ pw2)
{
    int idx = blockIdx.x * 256 + threadIdx.x;
    if (idx >= NSPLIT) return;

    const float* src;
    h16* dst;
    int actside;
    if (idx < NX)            { src = x;      dst = x2;  actside = 1; }
    else if (idx < NX + NW)  { idx -= NX;  src = kv_w;   dst = w2;  actside = 0; }
    else                     { idx -= NX + NW; src = proj_w; dst = pw2; actside = 0; }

    int row = idx >> 8, col = idx & 255;
    float v = src[idx];
    h16 hi = __float2half_rn(v);
    h16* dp = dst + (size_t)row * K2 + col;
    dp[0]   = hi;
    dp[256] = actside ? __float2half_rn(v - __half2float(hi)) : hi;
}

// ---------------------------------------------------------------------------
// fp16 tensor-core GEMM: C[M,N] = A2[M,512] @ B2[N,512]^T + bias
// OUTH=1 -> h16 output, OUTH=0 -> fp32 output.
// ---------------------------------------------------------------------------
template<int BN, int OUTH>
__global__ void __launch_bounds__(256, 2)
gemm_f16(const h16* __restrict__ Amat, const h16* __restrict__ Bmat,
         const float* __restrict__ bias, void* __restrict__ Cmat,
         int Mdim, int Ndim)
{
    constexpr int NT = BN / 32;
    constexpr int NP = BN / 64;
    constexpr unsigned STAGE = (128 + BN) * 80;

    extern __shared__ __align__(16) char smraw[];
    const unsigned smem0 = (unsigned)__cvta_generic_to_shared(smraw);

    const int tid  = threadIdx.x;
    const int lane = tid & 31;
    const int wrp  = tid >> 5;
    const int wm   = wrp & 1;
    const int wn   = wrp >> 1;
    const int m0   = blockIdx.y * 128;
    const int n0   = blockIdx.x * BN;

    const int rr = tid >> 2;
    const int qq = tid & 3;
    const h16* gA0 = Amat + (size_t)(m0 + rr) * K2 + qq * 8;
    const h16* gA1 = gA0 + (size_t)64 * K2;
    const h16* gB0 = Bmat + (size_t)(n0 + rr) * K2 + qq * 8;
    const h16* gB1 = gB0 + (size_t)64 * K2;
    const unsigned sA0 = smem0 + rr * 80 + qq * 16;
    const unsigned sA1 = sA0 + 5120;
    const unsigned sB0 = sA0 + 10240;
    const unsigned sB1 = sB0 + 5120;

    const unsigned almb = smem0 +
        (unsigned)((wm * 64 + (lane & 15)) * 80 + (lane >> 4) * 16);
    const unsigned blmb = smem0 + 10240u +
        (unsigned)((wn * (BN / 4) + (lane & 7) + ((lane >> 4) << 3)) * 80
                   + ((lane >> 3) & 1) * 16);

    float acc[4][NT][4];
#pragma unroll
    for (int mt = 0; mt < 4; mt++)
#pragma unroll
        for (int nt = 0; nt < NT; nt++)
#pragma unroll
            for (int e = 0; e < 4; e++) acc[mt][nt][e] = 0.0f;

#pragma unroll
    for (int st = 0; st < 3; st++) {
        unsigned off = (unsigned)st * STAGE;
        cp_async16(sA0 + off, gA0 + st * 32);
        cp_async16(sA1 + off, gA1 + st * 32);
        cp_async16(sB0 + off, gB0 + st * 32);
        if (BN == 128) cp_async16(sB1 + off, gB1 + st * 32);
        cp_commit();
    }

    const int T = K2 / 32;
    for (int t = 0; t < T; t++) {
        if (t < T - 2) cp_wait2();
        else           cp_wait0();
        __syncthreads();

        if (t + 3 < T) {
            const unsigned off = (unsigned)((t + 3) & 3) * STAGE;
            const int kt = t + 3;
            cp_async16(sA0 + off, gA0 + kt * 32);
            cp_async16(sA1 + off, gA1 + kt * 32);
            cp_async16(sB0 + off, gB0 + kt * 32);
            if (BN == 128) cp_async16(sB1 + off, gB1 + kt * 32);
            cp_commit();
        }

        const unsigned so = (unsigned)(t & 3) * STAGE;
#pragma unroll
        for (int ks = 0; ks < 2; ks++) {
            uint32_t afr[4][4];
            uint32_t bfr[NP][4];
#pragma unroll
            for (int mt = 0; mt < 4; mt++)
                ldmx4(afr[mt][0], afr[mt][1], afr[mt][2], afr[mt][3],
                      almb + so + mt * 1280 + ks * 32);
#pragma unroll
            for (int np = 0; np < NP; np++)
                ldmx4(bfr[np][0], bfr[np][1], bfr[np][2], bfr[np][3],
                      blmb + so + np * 1280 + ks * 32);
#pragma unroll
            for (int mt = 0; mt < 4; mt++) {
#pragma unroll
                for (int nt = 0; nt < NT; nt++) {
                    mma16816(acc[mt][nt][0], acc[mt][nt][1],
                             acc[mt][nt][2], acc[mt][nt][3],
                             afr[mt][0], afr[mt][1], afr[mt][2], afr[mt][3],
                             bfr[nt >> 1][(nt & 1) * 2],
                             bfr[nt >> 1][(nt & 1) * 2 + 1]);
                }
            }
        }
    }

    float2 bv[NT];
#pragma unroll
    for (int nt = 0; nt < NT; nt++)
        bv[nt] = *(const float2*)&bias[n0 + wn * (BN / 4) + nt * 8 + (lane & 3) * 2];

#pragma unroll
    for (int mt = 0; mt < 4; mt++) {
        const int row = m0 + wm * 64 + mt * 16 + (lane >> 2);
#pragma unroll
        for (int nt = 0; nt < NT; nt++) {
            const int col = n0 + wn * (BN / 4) + nt * 8 + (lane & 3) * 2;
            float v00 = acc[mt][nt][0] + bv[nt].x;
            float v01 = acc[mt][nt][1] + bv[nt].y;
            float v10 = acc[mt][nt][2] + bv[nt].x;
            float v11 = acc[mt][nt][3] + bv[nt].y;
            if (OUTH) {
                h16* Cm = (h16*)Cmat;
                *(half2*)&Cm[(size_t)row * Ndim + col]       = __floats2half2_rn(v00, v01);
                *(half2*)&Cm[(size_t)(row + 8) * Ndim + col] = __floats2half2_rn(v10, v11);
            } else {
                float* Cf = (float*)Cmat;
                *(float2*)&Cf[(size_t)row * Ndim + col]       = make_float2(v00, v01);
                *(float2*)&Cf[(size_t)(row + 8) * Ndim + col] = make_float2(v10, v11);
            }
        }
    }
}

// ---------------------------------------------------------------------------
// Tensor-core neighborhood attention (static warp schedule, lean exp phase).
// Block = (8x8 pixel tile, head, batch). 64 tasks share a 14x14 window.
// Columns padded 196 -> 256 (16 k16-tiles); warp w owns tiles {w, w+8}.
//   S[64x256] = Q[64x32] @ K[256x32]^T   (K rows 196-255 zeroed)
//   P = exp(S + bias) masked per task's 7x7 window (no max shift)
//   O[64x48] = P[64x256] @ Vt[48x256]^T  (Vt row 32 = ones -> col 32 = z)
//   out = O / z, stored as split-fp16 [hi, lo].
// ---------------------------------------------------------------------------
#define SM_Q  0        // 64 x 80B     = 5120
#define SM_K  5120     // 256 x 80B    = 20480
#define SM_VT 25600    // 48 x 528B    = 25344
#define SM_P  50944    // 64 x 528B    = 33792
#define SM_RS 84736    // 169 x 4B
#define SM_ZS 85416    // 64 x 4B
#define NATT_SMEM 85760

// mask + bias + exp with hoisted row constants:
// bias idx = rowbias + wr*13 + wc (precomputed colterm ct); valid iff
// wr-ar in [0,7) and wc-jc in [0,7).
__device__ __forceinline__ float nat_e(float s, int wr, int wc, int ct,
                                       int ar, int jc, int rb,
                                       const float* __restrict__ rs)
{
    if ((unsigned)(wr - ar) < 7u && (unsigned)(wc - jc) < 7u)
        return __expf(s + rs[rb + ct]);
    return 0.0f;
}

__global__ void __launch_bounds__(256, 2)
natt_mma_kernel(const float* __restrict__ q_extra,
                const float* __restrict__ rpb)
{
    extern __shared__ __align__(16) char smraw[];
    const unsigned sm0 = (unsigned)__cvta_generic_to_shared(smraw);
    float* rs = (float*)(smraw + SM_RS);

    const int tid  = threadIdx.x;
    const int lane = tid & 31;
    const int w    = tid >> 5;
    const int bb   = blockIdx.z;
    const int h    = blockIdx.y;
    const int i0   = (blockIdx.x / 7) * 8;
    const int j0   = (blockIdx.x % 7) * 8;
    const int u0   = min(max(i0 - 3, 0), HH - 14);
    const int v0   = min(max(j0 - 3, 0), WW - 14);
    const float scale = 0.17677669529663687f;

    // ---- stage phase ----
    for (int idx = tid; idx < RPB_S * RPB_S; idx += 256)
        rs[idx] = rpb[h * RPB_S * RPB_S + idx];

    // zero K pad rows 196-255 (60 rows x 5 uint4)
    for (int idx = tid; idx < 300; idx += 256)
        *(uint4*)(smraw + SM_K + (196 + idx / 5) * 80 + (idx % 5) * 16) =
            make_uint4(0, 0, 0, 0);
    // zero all of Vt (48 rows x 33 uint4)
    for (int idx = tid; idx < 48 * 33; idx += 256)
        *(uint4*)(smraw + SM_VT + (idx / 33) * 528 + (idx % 33) * 16) =
            make_uint4(0, 0, 0, 0);

    // Q: 64 tasks x 32 dims fp32 -> fp16 * scale
    for (int idx = tid; idx < 512; idx += 256) {
        int task = idx >> 3, c4 = idx & 7;
        int ii = i0 + (task >> 3), jj = j0 + (task & 7);
        int pix = (bb * HH + ii) * WW + jj;
        float4 v = *(const float4*)&q_extra[(size_t)pix * CC + h * 32 + c4 * 4];
        half2* dq = (half2*)(smraw + SM_Q + task * 80 + c4 * 8);
        dq[0] = __floats2half2_rn(v.x * scale, v.y * scale);
        dq[1] = __floats2half2_rn(v.z * scale, v.w * scale);
    }

    // K: 196 window pixels x 32 h16 (4 x 16B each)
    for (int idx = tid; idx < 196 * 4; idx += 256) {
        int wp = idx >> 2, c = idx & 3;
        int wr = wp / 14, wc = wp % 14;
        int pix = (bb * HH + u0 + wr) * WW + v0 + wc;
        uint4 val = *(const uint4*)(g_kv + (size_t)pix * KV_N + h * 32 + c * 8);
        *(uint4*)(smraw + SM_K + wp * 80 + c * 16) = val;
    }
    __syncthreads();   // Vt zero must complete before transpose fill

    // Vt: transpose V window into [dim][wp] (stride 528B)
    for (int idx = tid; idx < 196 * 32; idx += 256) {
        int wp = idx >> 5, d = idx & 31;
        int wr = wp / 14, wc = wp % 14;
        int pix = (bb * HH + u0 + wr) * WW + v0 + wc;
        h16 v = g_kv[(size_t)pix * KV_N + 256 + h * 32 + d];
        *(h16*)(smraw + SM_VT + d * 528 + wp * 2) = v;
    }
    // ones row (dim 32) for z over the 196 real columns
    for (int idx = tid; idx < 196; idx += 256)
        *(h16*)(smraw + SM_VT + 32 * 528 + idx * 2) = __float2half_rn(1.0f);

    __syncthreads();

    // ---- per-thread row constants (8 rows: [half][mt]) ----
    int rowar[2][4], rowjc[2][4], rowbias[2][4];
#pragma unroll
    for (int hf = 0; hf < 2; hf++) {
#pragma unroll
        for (int mt = 0; mt < 4; mt++) {
            const int row = mt * 16 + (lane >> 2) + hf * 8;
            const int ii = i0 + (row >> 3), jj = j0 + (row & 7);
            const int ar  = min(max(ii - 3, 0), HH - 7) - u0;
            const int pis = 3 + max(3 - ii, 0) + min(HH - 4 - ii, 0);
            const int jc  = min(max(jj - 3, 0), WW - 7) - v0;
            const int pjs = 3 + max(3 - jj, 0) + min(WW - 4 - jj, 0);
            rowar[hf][mt]   = ar;
            rowjc[hf][mt]   = jc;
            rowbias[hf][mt] = (pis - ar) * RPB_S + (pjs - jc);
        }
    }

    // ---- QK phase: warp w owns column tiles {w, w+8}; fully static ----
    uint32_t afr[4][2][4];
#pragma unroll
    for (int mt = 0; mt < 4; mt++)
#pragma unroll
        for (int ks = 0; ks < 2; ks++)
            ldmx4(afr[mt][ks][0], afr[mt][ks][1], afr[mt][ks][2], afr[mt][ks][3],
                  sm0 + SM_Q + (mt * 16 + (lane & 15)) * 80 + (lane >> 4) * 16 + ks * 32);

    const int cq = (lane & 3) * 2;
#pragma unroll
    for (int pi = 0; pi < 2; pi++) {
        const int p = w + pi * 8;          // column k16-tile index (0..15)
        float qc0[4][4], qc1[4][4];
#pragma unroll
        for (int mt = 0; mt < 4; mt++)
#pragma unroll
            for (int e = 0; e < 4; e++) { qc0[mt][e] = 0.0f; qc1[mt][e] = 0.0f; }

#pragma unroll
        for (int ks = 0; ks < 2; ks++) {
            uint32_t bf[4];
            ldmx4(bf[0], bf[1], bf[2], bf[3],
                  sm0 + SM_K + (p * 16 + (lane & 7) + ((lane >> 4) << 3)) * 80
                  + ((lane >> 3) & 1) * 16 + ks * 32);
#pragma unroll
            for (int mt = 0; mt < 4; mt++) {
                mma16816(qc0[mt][0], qc0[mt][1], qc0[mt][2], qc0[mt][3],
                         afr[mt][ks][0], afr[mt][ks][1], afr[mt][ks][2], afr[mt][ks][3],
                         bf[0], bf[1]);
                mma16816(qc1[mt][0], qc1[mt][1], qc1[mt][2], qc1[mt][3],
                         afr[mt][ks][0], afr[mt][ks][1], afr[mt][ks][2], afr[mt][ks][3],
                         bf[2], bf[3]);
            }
        }

        // bias + mask + exp -> P (fp16, unnormalized)
#pragma unroll
        for (int grp = 0; grp < 2; grp++) {
            const int c0  = p * 16 + grp * 8 + cq;
            const int c1  = c0 + 1;
            const int wr0 = (c0 * 4682) >> 16;
            const int wc0 = c0 - wr0 * 14;
            const int wr1 = (c1 * 4682) >> 16;
            const int wc1 = c1 - wr1 * 14;
            const int ct0 = wr0 * RPB_S + wc0;
            const int ct1 = wr1 * RPB_S + wc1;
#pragma unroll
            for (int mt = 0; mt < 4; mt++) {
                const int r0 = mt * 16 + (lane >> 2);
                float s00 = grp ? qc1[mt][0] : qc0[mt][0];
                float s01 = grp ? qc1[mt][1] : qc0[mt][1];
                float s10 = grp ? qc1[mt][2] : qc0[mt][2];
                float s11 = grp ? qc1[mt][3] : qc0[mt][3];
                float e00 = nat_e(s00, wr0, wc0, ct0, rowar[0][mt], rowjc[0][mt], rowbias[0][mt], rs);
                float e01 = nat_e(s01, wr1, wc1, ct1, rowar[0][mt], rowjc[0][mt], rowbias[0][mt], rs);
                float e10 = nat_e(s10, wr0, wc0, ct0, rowar[1][mt], rowjc[1][mt], rowbias[1][mt], rs);
                float e11 = nat_e(s11, wr1, wc1, ct1, rowar[1][mt], rowjc[1][mt], rowbias[1][mt], rs);
                *(half2*)(smraw + SM_P + r0 * 528 + c0 * 2)       = __floats2half2_rn(e00, e01);
                *(half2*)(smraw + SM_P + (r0 + 8) * 528 + c0 * 2) = __floats2half2_rn(e10, e11);
            }
        }
    }

    __syncthreads();

    // ---- AV phase: O[64x48] = P[64x256] @ Vt[48x256]^T ----
    const int  mtav    = w & 3;
    const bool hi_half = (w >= 4);
    float av[3][4];
#pragma unroll
    for (int u2 = 0; u2 < 3; u2++)
#pragma unroll
        for (int e = 0; e < 4; e++) av[u2][e] = 0.0f;

    const unsigned pa = sm0 + SM_P +
        (mtav * 16 + (lane & 15)) * 528 + (lane >> 4) * 16;
    const unsigned pb = sm0 + SM_VT +
        ((hi_half ? 16 : 0) + (lane & 7) + ((lane >> 4) << 3)) * 528
        + ((lane >> 3) & 1) * 16;
    const unsigned pb2 = sm0 + SM_VT +
        (32 + (lane & 7) + ((lane >> 4) << 3)) * 528 + ((lane >> 3) & 1) * 16;

#pragma unroll
    for (int ks = 0; ks < 16; ks++) {
        uint32_t a4[4], b4[4];
        ldmx4(a4[0], a4[1], a4[2], a4[3], pa + ks * 32);
        ldmx4(b4[0], b4[1], b4[2], b4[3], pb + ks * 32);
        mma16816(av[0][0], av[0][1], av[0][2], av[0][3],
                 a4[0], a4[1], a4[2], a4[3], b4[0], b4[1]);
        mma16816(av[1][0], av[1][1], av[1][2], av[1][3],
                 a4[0], a4[1], a4[2], a4[3], b4[2], b4[3]);
        if (hi_half) {
            uint32_t b2[4];
            ldmx4(b2[0], b2[1], b2[2], b2[3], pb2 + ks * 32);
            mma16816(av[2][0], av[2][1], av[2][2], av[2][3],
                     a4[0], a4[1], a4[2], a4[3], b2[0], b2[1]);
        }
    }

    // z (col 32) -> smem
    if (hi_half && (lane & 3) == 0) {
        const int r0 = mtav * 16 + (lane >> 2);
        *(float*)(smraw + SM_ZS + r0 * 4)       = av[2][0];
        *(float*)(smraw + SM_ZS + (r0 + 8) * 4) = av[2][2];
    }
    __syncthreads();

    // ---- normalize + store split-fp16 ----
    {
        const int r0 = mtav * 16 + (lane >> 2);
        const float zi0 = __frcp_rn(*(float*)(smraw + SM_ZS + r0 * 4));
        const float zi1 = __frcp_rn(*(float*)(smraw + SM_ZS + (r0 + 8) * 4));
        const int pix0 = (bb * HH + i0 + (r0 >> 3)) * WW + j0 + (r0 & 7);
        const int pix1 = (bb * HH + i0 + (r0 >> 3) + 1) * WW + j0 + (r0 & 7);
#pragma unroll
        for (int nti = 0; nti < 2; nti++) {
            const int d0 = (hi_half ? 16 : 0) + nti * 8 + (lane & 3) * 2;
            float o00 = av[nti][0] * zi0, o01 = av[nti][1] * zi0;
            float o10 = av[nti][2] * zi1, o11 = av[nti][3] * zi1;

            h16* dst0 = g_att2 + (size_t)pix0 * K2 + h * 32 + d0;
            half2 h0 = __floats2half2_rn(o00, o01);
            *(half2*)dst0 = h0;
            float2 f0 = __half22float2(h0);
            *(half2*)(dst0 + 256) = __floats2half2_rn(o00 - f0.x, o01 - f0.y);

            h16* dst1 = g_att2 + (size_t)pix1 * K2 + h * 32 + d0;
            half2 h1 = __floats2half2_rn(o10, o11);
            *(half2*)dst1 = h1;
            float2 f1 = __half22float2(h1);
            *(half2*)(dst1 + 256) = __floats2half2_rn(o10 - f1.x, o11 - f1.y);
        }
    }
}

// ---------------------------------------------------------------------------
// Launch
// ---------------------------------------------------------------------------
extern "C" void kernel_launch(void* const* d_in, const int* in_sizes, int n_in,
                              void* d_out, int out_size)
{
    const float* x       = (const float*)d_in[0];
    const float* q_extra = (const float*)d_in[1];
    const float* kv_w    = (const float*)d_in[2];
    const float* kv_b    = (const float*)d_in[3];
    const float* rpb     = (const float*)d_in[4];
    const float* proj_w  = (const float*)d_in[5];
    const float* proj_b  = (const float*)d_in[6];
    float* out = (float*)d_out;

    h16 *kv_ptr = nullptr, *x2_ptr = nullptr, *att2_ptr = nullptr;
    h16 *w2_ptr = nullptr, *pw2_ptr = nullptr;
    cudaGetSymbolAddress((void**)&kv_ptr,   g_kv);
    cudaGetSymbolAddress((void**)&x2_ptr,   g_x2);
    cudaGetSymbolAddress((void**)&att2_ptr, g_att2);
    cudaGetSymbolAddress((void**)&w2_ptr,   g_w2);
    cudaGetSymbolAddress((void**)&pw2_ptr,  g_pw2);

    const int smem128 = 4 * (128 + 128) * 80;   // 81920
    const int smem64  = 4 * (128 + 64)  * 80;   // 61440
    cudaFuncSetAttribute(gemm_f16<128, 1>,
                         cudaFuncAttributeMaxDynamicSharedMemorySize, smem128);
    cudaFuncSetAttribute(gemm_f16<64, 0>,
                         cudaFuncAttributeMaxDynamicSharedMemorySize, smem64);
    cudaFuncSetAttribute(natt_mma_kernel,
                         cudaFuncAttributeMaxDynamicSharedMemorySize, NATT_SMEM);

    // 0) fused split: fp32 -> 2-term fp16 (x, kv_w, proj_w)
    split_all_kernel<<<(NSPLIT + 255) / 256, 256>>>(
        x, kv_w, proj_w, x2_ptr, w2_ptr, pw2_ptr);

    // 1) kv = x @ kv_w^T + kv_b   (fp16 output)
    gemm_f16<128, 1><<<dim3(KV_N / 128, NPIX / 128), 256, smem128>>>(
        x2_ptr, w2_ptr, kv_b, kv_ptr, NPIX, KV_N);

    // 2) tensor-core neighborhood attention: 8x8 tiles -> grid (49, 8, 2)
    natt_mma_kernel<<<dim3(49, HEADS, BB), 256, NATT_SMEM>>>(q_extra, rpb);

    // 3) out = att @ proj_w^T + proj_b   (fp32 output)
    gemm_f16<64, 0><<<dim3(CC / 64, NPIX / 128), 256, smem64>>>(
        att2_ptr, pw2_ptr, proj_b, out, NPIX, CC);
}

// round 14
// speedup vs baseline: 1.7157x; 1.1562x over previous
#include <cuda_runtime.h>
#include <cuda_fp16.h>
#include <cstdint>

// Problem constants
#define BB 2
#define HH 56
#define WW 56
#define CC 256
#define HEADS 8
#define NPIX (BB*HH*WW)          // 6272
#define KV_N 512
#define RPB_S 13
#define K2 512                   // 2 * CC (split-fp16 K dimension)

typedef __half h16;

// Scratch (no cudaMalloc allowed)
__device__ h16 g_kv  [NPIX * KV_N];   // fp16: key c[0:256], val c[256:512]
__device__ h16 g_x2  [NPIX * K2];     // [xh, xl]
__device__ h16 g_att2[NPIX * K2];     // [ah, al]
__device__ h16 g_w2  [KV_N * K2];     // [wh, wh]
__device__ h16 g_pw2 [CC   * K2];     // [wh, wh]

// ---------------------------------------------------------------------------
// PTX helpers (scalar args only)
// ---------------------------------------------------------------------------
__device__ __forceinline__ void cp_async16(unsigned dst, const void* src)
{
    asm volatile("cp.async.cg.shared.global [%0], [%1], 16;"
                 :: "r"(dst), "l"(src));
}
__device__ __forceinline__ void cp_commit()
{
    asm volatile("cp.async.commit_group;");
}
__device__ __forceinline__ void cp_wait2()
{
    asm volatile("cp.async.wait_group 2;");
}
__device__ __forceinline__ void cp_wait0()
{
    asm volatile("cp.async.wait_group 0;");
}
__device__ __forceinline__ void ldmx4(uint32_t& r0, uint32_t& r1,
                                      uint32_t& r2, uint32_t& r3, unsigned addr)
{
    asm volatile("ldmatrix.sync.aligned.m8n8.x4.shared.b16 {%0,%1,%2,%3}, [%4];"
                 : "=r"(r0), "=r"(r1), "=r"(r2), "=r"(r3) : "r"(addr));
}
__device__ __forceinline__ void ldmx4t(uint32_t& r0, uint32_t& r1,
                                       uint32_t& r2, uint32_t& r3, unsigned addr)
{
    asm volatile("ldmatrix.sync.aligned.m8n8.x4.trans.shared.b16 {%0,%1,%2,%3}, [%4];"
                 : "=r"(r0), "=r"(r1), "=r"(r2), "=r"(r3) : "r"(addr));
}
__device__ __forceinline__ void mma16816(float& d0, float& d1, float& d2, float& d3,
                                         uint32_t a0, uint32_t a1, uint32_t a2, uint32_t a3,
                                         uint32_t b0, uint32_t b1)
{
    asm volatile("mma.sync.aligned.m16n8k16.row.col.f32.f16.f16.f32 "
                 "{%0,%1,%2,%3}, {%4,%5,%6,%7}, {%8,%9}, {%0,%1,%2,%3};"
                 : "+f"(d0), "+f"(d1), "+f"(d2), "+f"(d3)
                 : "r"(a0), "r"(a1), "r"(a2), "r"(a3), "r"(b0), "r"(b1));
}

// ---------------------------------------------------------------------------
// fused split (vectorized, 2 cols/thread):
// fp32 [rows][256] -> fp16 [rows][512] for x, kv_w, proj_w.
// ---------------------------------------------------------------------------
#define NX (NPIX * CC)
#define NW (KV_N * CC)
#define NPW (CC * CC)
#define NSPLIT (NX + NW + NPW)

__global__ void split_all_kernel(const float* __restrict__ x,
                                 const float* __restrict__ kv_w,
                                 const float* __restrict__ proj_w,
                                 h16* __restrict__ x2,
                                 h16* __restrict__ w2,
                                 h16* __restrict__ pw2)
{
    int idx = blockIdx.x * 256 + threadIdx.x;
    if (idx >= NSPLIT / 2) return;
    int e = idx * 2;

    const float* src;
    h16* dst;
    int actside;
    if (e < NX)            { src = x;      dst = x2;  actside = 1; }
    else if (e < NX + NW)  { e -= NX;  src = kv_w;   dst = w2;  actside = 0; }
    else                   { e -= NX + NW; src = proj_w; dst = pw2; actside = 0; }

    int row = e >> 8, col = e & 255;
    float2 v = *(const float2*)&src[e];
    half2 hi = __floats2half2_rn(v.x, v.y);
    h16* dp = dst + (size_t)row * K2 + col;
    *(half2*)dp = hi;
    if (actside) {
        float2 f = __half22float2(hi);
        *(half2*)(dp + 256) = __floats2half2_rn(v.x - f.x, v.y - f.y);
    } else {
        *(half2*)(dp + 256) = hi;
    }
}

// ---------------------------------------------------------------------------
// fp16 tensor-core GEMM: C[M,N] = A2[M,512] @ B2[N,512]^T + bias
// OUTH=1 -> h16 output, OUTH=0 -> fp32 output.
// ---------------------------------------------------------------------------
template<int BN, int OUTH>
__global__ void __launch_bounds__(256, 2)
gemm_f16(const h16* __restrict__ Amat, const h16* __restrict__ Bmat,
         const float* __restrict__ bias, void* __restrict__ Cmat,
         int Mdim, int Ndim)
{
    constexpr int NT = BN / 32;
    constexpr int NP = BN / 64;
    constexpr unsigned STAGE = (128 + BN) * 80;

    extern __shared__ __align__(16) char smraw[];
    const unsigned smem0 = (unsigned)__cvta_generic_to_shared(smraw);

    const int tid  = threadIdx.x;
    const int lane = tid & 31;
    const int wrp  = tid >> 5;
    const int wm   = wrp & 1;
    const int wn   = wrp >> 1;
    const int m0   = blockIdx.y * 128;
    const int n0   = blockIdx.x * BN;

    const int rr = tid >> 2;
    const int qq = tid & 3;
    const h16* gA0 = Amat + (size_t)(m0 + rr) * K2 + qq * 8;
    const h16* gA1 = gA0 + (size_t)64 * K2;
    const h16* gB0 = Bmat + (size_t)(n0 + rr) * K2 + qq * 8;
    const h16* gB1 = gB0 + (size_t)64 * K2;
    const unsigned sA0 = smem0 + rr * 80 + qq * 16;
    const unsigned sA1 = sA0 + 5120;
    const unsigned sB0 = sA0 + 10240;
    const unsigned sB1 = sB0 + 5120;

    const unsigned almb = smem0 +
        (unsigned)((wm * 64 + (lane & 15)) * 80 + (lane >> 4) * 16);
    const unsigned blmb = smem0 + 10240u +
        (unsigned)((wn * (BN / 4) + (lane & 7) + ((lane >> 4) << 3)) * 80
                   + ((lane >> 3) & 1) * 16);

    float acc[4][NT][4];
#pragma unroll
    for (int mt = 0; mt < 4; mt++)
#pragma unroll
        for (int nt = 0; nt < NT; nt++)
#pragma unroll
            for (int e = 0; e < 4; e++) acc[mt][nt][e] = 0.0f;

#pragma unroll
    for (int st = 0; st < 3; st++) {
        unsigned off = (unsigned)st * STAGE;
        cp_async16(sA0 + off, gA0 + st * 32);
        cp_async16(sA1 + off, gA1 + st * 32);
        cp_async16(sB0 + off, gB0 + st * 32);
        if (BN == 128) cp_async16(sB1 + off, gB1 + st * 32);
        cp_commit();
    }

    const int T = K2 / 32;
    for (int t = 0; t < T; t++) {
        if (t < T - 2) cp_wait2();
        else           cp_wait0();
        __syncthreads();

        if (t + 3 < T) {
            const unsigned off = (unsigned)((t + 3) & 3) * STAGE;
            const int kt = t + 3;
            cp_async16(sA0 + off, gA0 + kt * 32);
            cp_async16(sA1 + off, gA1 + kt * 32);
            cp_async16(sB0 + off, gB0 + kt * 32);
            if (BN == 128) cp_async16(sB1 + off, gB1 + kt * 32);
            cp_commit();
        }

        const unsigned so = (unsigned)(t & 3) * STAGE;
#pragma unroll
        for (int ks = 0; ks < 2; ks++) {
            uint32_t afr[4][4];
            uint32_t bfr[NP][4];
#pragma unroll
            for (int mt = 0; mt < 4; mt++)
                ldmx4(afr[mt][0], afr[mt][1], afr[mt][2], afr[mt][3],
                      almb + so + mt * 1280 + ks * 32);
#pragma unroll
            for (int np = 0; np < NP; np++)
                ldmx4(bfr[np][0], bfr[np][1], bfr[np][2], bfr[np][3],
                      blmb + so + np * 1280 + ks * 32);
#pragma unroll
            for (int mt = 0; mt < 4; mt++) {
#pragma unroll
                for (int nt = 0; nt < NT; nt++) {
                    mma16816(acc[mt][nt][0], acc[mt][nt][1],
                             acc[mt][nt][2], acc[mt][nt][3],
                             afr[mt][0], afr[mt][1], afr[mt][2], afr[mt][3],
                             bfr[nt >> 1][(nt & 1) * 2],
                             bfr[nt >> 1][(nt & 1) * 2 + 1]);
                }
            }
        }
    }

    float2 bv[NT];
#pragma unroll
    for (int nt = 0; nt < NT; nt++)
        bv[nt] = *(const float2*)&bias[n0 + wn * (BN / 4) + nt * 8 + (lane & 3) * 2];

#pragma unroll
    for (int mt = 0; mt < 4; mt++) {
        const int row = m0 + wm * 64 + mt * 16 + (lane >> 2);
#pragma unroll
        for (int nt = 0; nt < NT; nt++) {
            const int col = n0 + wn * (BN / 4) + nt * 8 + (lane & 3) * 2;
            float v00 = acc[mt][nt][0] + bv[nt].x;
            float v01 = acc[mt][nt][1] + bv[nt].y;
            float v10 = acc[mt][nt][2] + bv[nt].x;
            float v11 = acc[mt][nt][3] + bv[nt].y;
            if (OUTH) {
                h16* Cm = (h16*)Cmat;
                *(half2*)&Cm[(size_t)row * Ndim + col]       = __floats2half2_rn(v00, v01);
                *(half2*)&Cm[(size_t)(row + 8) * Ndim + col] = __floats2half2_rn(v10, v11);
            } else {
                float* Cf = (float*)Cmat;
                *(float2*)&Cf[(size_t)row * Ndim + col]       = make_float2(v00, v01);
                *(float2*)&Cf[(size_t)(row + 8) * Ndim + col] = make_float2(v10, v11);
            }
        }
    }
}

// ---------------------------------------------------------------------------
// Tensor-core neighborhood attention, v3 (fixed V staging offset):
//  - V stored row-major [wp][40 dims] like K; AV B-operand via ldmatrix.trans
//    (no scalar transpose). V dim 32 = 1.0 -> O col 32 = softmax z.
//  - columns padded only to 208 (13 k16-tiles); warps 0-4 take 2 QK tiles,
//    5-7 take 1 (uniform branch, static accumulators).
// Block = (8x8 pixel tile, head, batch); 2 CTAs/SM.
// ---------------------------------------------------------------------------
#define SM_Q  0        // 64 x 80B   = 5120
#define SM_K  5120     // 208 x 80B  = 16640
#define SM_V  21760    // 212 x 80B  = 16960
#define SM_P  38720    // 64 x 432B  = 27648
#define SM_RS 66368    // 169 x 4B
#define SM_ZS 67048    // 64 x 4B
#define NATT_SMEM 67312

// mask + bias + exp with hoisted row constants
__device__ __forceinline__ float nat_e(float s, int wr, int wc, int ct,
                                       int ar, int jc, int rb,
                                       const float* __restrict__ rs)
{
    if ((unsigned)(wr - ar) < 7u && (unsigned)(wc - jc) < 7u)
        return __expf(s + rs[rb + ct]);
    return 0.0f;
}

__global__ void __launch_bounds__(256, 2)
natt_mma_kernel(const float* __restrict__ q_extra,
                const float* __restrict__ rpb)
{
    extern __shared__ __align__(16) char smraw[];
    const unsigned sm0 = (unsigned)__cvta_generic_to_shared(smraw);
    float* rs = (float*)(smraw + SM_RS);

    const int tid  = threadIdx.x;
    const int lane = tid & 31;
    const int w    = tid >> 5;
    const int bb   = blockIdx.z;
    const int h    = blockIdx.y;
    const int i0   = (blockIdx.x / 7) * 8;
    const int j0   = (blockIdx.x % 7) * 8;
    const int u0   = min(max(i0 - 3, 0), HH - 14);
    const int v0   = min(max(j0 - 3, 0), WW - 14);
    const float scale = 0.17677669529663687f;

    // ---- stage phase ----
    for (int idx = tid; idx < RPB_S * RPB_S; idx += 256)
        rs[idx] = rpb[h * RPB_S * RPB_S + idx];

    // zero K pad rows 196-207 (12 x 5 uint4)
    if (tid < 60)
        *(uint4*)(smraw + SM_K + (196 + tid / 5) * 80 + (tid % 5) * 16) =
            make_uint4(0, 0, 0, 0);
    // zero V pad rows 196-211 (16 x 5 uint4)
    if (tid >= 60 && tid < 140) {
        int t2 = tid - 60;
        *(uint4*)(smraw + SM_V + (196 + t2 / 5) * 80 + (t2 % 5) * 16) =
            make_uint4(0, 0, 0, 0);
    }

    // Q: 64 tasks x 32 dims fp32 -> fp16 * scale
    for (int idx = tid; idx < 512; idx += 256) {
        int task = idx >> 3, c4 = idx & 7;
        int ii = i0 + (task >> 3), jj = j0 + (task & 7);
        int pix = (bb * HH + ii) * WW + jj;
        float4 v = *(const float4*)&q_extra[(size_t)pix * CC + h * 32 + c4 * 4];
        half2* dq = (half2*)(smraw + SM_Q + task * 80 + c4 * 8);
        dq[0] = __floats2half2_rn(v.x * scale, v.y * scale);
        dq[1] = __floats2half2_rn(v.z * scale, v.w * scale);
    }

    // K + V: 196 window pixels, 4 uint4 K + 4 uint4 V each (coalesced).
    // src is uint4* over h16: V block (+256 h16) = src[32].
    for (int idx = tid; idx < 196 * 8; idx += 256) {
        int wp = idx >> 3, c = idx & 7;
        int wr = wp / 14, wc = wp % 14;
        int pix = (bb * HH + u0 + wr) * WW + v0 + wc;
        const uint4* src = (const uint4*)(g_kv + (size_t)pix * KV_N + h * 32);
        if (c < 4)
            *(uint4*)(smraw + SM_K + wp * 80 + c * 16) = src[c];
        else
            *(uint4*)(smraw + SM_V + wp * 80 + (c - 4) * 16) = src[32 + (c - 4)];
    }
    // V tail: dim 32 = 1.0 (z column), dims 33-39 = 0
    for (int idx = tid; idx < 196; idx += 256)
        *(uint4*)(smraw + SM_V + idx * 80 + 64) = make_uint4(0x3C00u, 0, 0, 0);

    __syncthreads();

    // ---- per-thread row constants (8 rows: [half][mt]) ----
    int rowar[2][4], rowjc[2][4], rowbias[2][4];
#pragma unroll
    for (int hf = 0; hf < 2; hf++) {
#pragma unroll
        for (int mt = 0; mt < 4; mt++) {
            const int row = mt * 16 + (lane >> 2) + hf * 8;
            const int ii = i0 + (row >> 3), jj = j0 + (row & 7);
            const int ar  = min(max(ii - 3, 0), HH - 7) - u0;
            const int pis = 3 + max(3 - ii, 0) + min(HH - 4 - ii, 0);
            const int jc  = min(max(jj - 3, 0), WW - 7) - v0;
            const int pjs = 3 + max(3 - jj, 0) + min(WW - 4 - jj, 0);
            rowar[hf][mt]   = ar;
            rowjc[hf][mt]   = jc;
            rowbias[hf][mt] = (pis - ar) * RPB_S + (pjs - jc);
        }
    }

    // ---- QK phase: warp w owns tile w, and tile w+8 if w < 5 ----
    uint32_t afr[4][2][4];
#pragma unroll
    for (int mt = 0; mt < 4; mt++)
#pragma unroll
        for (int ks = 0; ks < 2; ks++)
            ldmx4(afr[mt][ks][0], afr[mt][ks][1], afr[mt][ks][2], afr[mt][ks][3],
                  sm0 + SM_Q + (mt * 16 + (lane & 15)) * 80 + (lane >> 4) * 16 + ks * 32);

    const int cq = (lane & 3) * 2;
#pragma unroll
    for (int pi = 0; pi < 2; pi++) {
        if (pi == 1 && w >= 5) break;      // uniform per warp
        const int p = w + pi * 8;          // column k16-tile index (0..12)
        float qc0[4][4], qc1[4][4];
#pragma unroll
        for (int mt = 0; mt < 4; mt++)
#pragma unroll
            for (int e = 0; e < 4; e++) { qc0[mt][e] = 0.0f; qc1[mt][e] = 0.0f; }

#pragma unroll
        for (int ks = 0; ks < 2; ks++) {
            uint32_t bf[4];
            ldmx4(bf[0], bf[1], bf[2], bf[3],
                  sm0 + SM_K + (p * 16 + (lane & 7) + ((lane >> 4) << 3)) * 80
                  + ((lane >> 3) & 1) * 16 + ks * 32);
#pragma unroll
            for (int mt = 0; mt < 4; mt++) {
                mma16816(qc0[mt][0], qc0[mt][1], qc0[mt][2], qc0[mt][3],
                         afr[mt][ks][0], afr[mt][ks][1], afr[mt][ks][2], afr[mt][ks][3],
                         bf[0], bf[1]);
                mma16816(qc1[mt][0], qc1[mt][1], qc1[mt][2], qc1[mt][3],
                         afr[mt][ks][0], afr[mt][ks][1], afr[mt][ks][2], afr[mt][ks][3],
                         bf[2], bf[3]);
            }
        }

        // bias + mask + exp -> P (fp16, unnormalized)
#pragma unroll
        for (int grp = 0; grp < 2; grp++) {
            const int c0  = p * 16 + grp * 8 + cq;
            const int c1  = c0 + 1;
            const int wr0 = (c0 * 4682) >> 16;
            const int wc0 = c0 - wr0 * 14;
            const int wr1 = (c1 * 4682) >> 16;
            const int wc1 = c1 - wr1 * 14;
            const int ct0 = wr0 * RPB_S + wc0;
            const int ct1 = wr1 * RPB_S + wc1;
#pragma unroll
            for (int mt = 0; mt < 4; mt++) {
                const int r0 = mt * 16 + (lane >> 2);
                float s00 = grp ? qc1[mt][0] : qc0[mt][0];
                float s01 = grp ? qc1[mt][1] : qc0[mt][1];
                float s10 = grp ? qc1[mt][2] : qc0[mt][2];
                float s11 = grp ? qc1[mt][3] : qc0[mt][3];
                float e00 = nat_e(s00, wr0, wc0, ct0, rowar[0][mt], rowjc[0][mt], rowbias[0][mt], rs);
                float e01 = nat_e(s01, wr1, wc1, ct1, rowar[0][mt], rowjc[0][mt], rowbias[0][mt], rs);
                float e10 = nat_e(s10, wr0, wc0, ct0, rowar[1][mt], rowjc[1][mt], rowbias[1][mt], rs);
                float e11 = nat_e(s11, wr1, wc1, ct1, rowar[1][mt], rowjc[1][mt], rowbias[1][mt], rs);
                *(half2*)(smraw + SM_P + r0 * 432 + c0 * 2)       = __floats2half2_rn(e00, e01);
                *(half2*)(smraw + SM_P + (r0 + 8) * 432 + c0 * 2) = __floats2half2_rn(e10, e11);
            }
        }
    }

    __syncthreads();

    // ---- AV phase: O[64x40] = P[64x208] @ V[208x40] (B via ldmatrix.trans) ----
    const int  mtav    = w & 3;
    const bool hi_half = (w >= 4);
    float av[3][4];
#pragma unroll
    for (int u2 = 0; u2 < 3; u2++)
#pragma unroll
        for (int e = 0; e < 4; e++) av[u2][e] = 0.0f;

    const unsigned pa = sm0 + SM_P +
        (mtav * 16 + (lane & 15)) * 432 + (lane >> 4) * 16;
    // trans B: row = k (window pixel), byte col = dim*2
    const unsigned pb = sm0 + SM_V + (lane & 15) * 80 +
        (hi_half ? 32u : 0u) + (lane >> 4) * 16;
    const unsigned pb2 = sm0 + SM_V + (lane & 15) * 80 + 64 + (lane >> 4) * 16;

#pragma unroll
    for (int ks = 0; ks < 13; ks++) {
        uint32_t a4[4], b4[4];
        ldmx4(a4[0], a4[1], a4[2], a4[3], pa + ks * 32);
        ldmx4t(b4[0], b4[1], b4[2], b4[3], pb + ks * 1280);
        mma16816(av[0][0], av[0][1], av[0][2], av[0][3],
                 a4[0], a4[1], a4[2], a4[3], b4[0], b4[1]);
        mma16816(av[1][0], av[1][1], av[1][2], av[1][3],
                 a4[0], a4[1], a4[2], a4[3], b4[2], b4[3]);
        if (hi_half) {
            uint32_t b2[4];
            ldmx4t(b2[0], b2[1], b2[2], b2[3], pb2 + ks * 1280);
            mma16816(av[2][0], av[2][1], av[2][2], av[2][3],
                     a4[0], a4[1], a4[2], a4[3], b2[0], b2[1]);
        }
    }

    // z (col 32) -> smem
    if (hi_half && (lane & 3) == 0) {
        const int r0 = mtav * 16 + (lane >> 2);
        *(float*)(smraw + SM_ZS + r0 * 4)       = av[2][0];
        *(float*)(smraw + SM_ZS + (r0 + 8) * 4) = av[2][2];
    }
    __syncthreads();

    // ---- normalize + store split-fp16 ----
    {
        const int r0 = mtav * 16 + (lane >> 2);
        const float zi0 = __frcp_rn(*(float*)(smraw + SM_ZS + r0 * 4));
        const float zi1 = __frcp_rn(*(float*)(smraw + SM_ZS + (r0 + 8) * 4));
        const int pix0 = (bb * HH + i0 + (r0 >> 3)) * WW + j0 + (r0 & 7);
        const int pix1 = (bb * HH + i0 + (r0 >> 3) + 1) * WW + j0 + (r0 & 7);
#pragma unroll
        for (int nti = 0; nti < 2; nti++) {
            const int d0 = (hi_half ? 16 : 0) + nti * 8 + (lane & 3) * 2;
            float o00 = av[nti][0] * zi0, o01 = av[nti][1] * zi0;
            float o10 = av[nti][2] * zi1, o11 = av[nti][3] * zi1;

            h16* dst0 = g_att2 + (size_t)pix0 * K2 + h * 32 + d0;
            half2 h0 = __floats2half2_rn(o00, o01);
            *(half2*)dst0 = h0;
            float2 f0 = __half22float2(h0);
            *(half2*)(dst0 + 256) = __floats2half2_rn(o00 - f0.x, o01 - f0.y);

            h16* dst1 = g_att2 + (size_t)pix1 * K2 + h * 32 + d0;
            half2 h1 = __floats2half2_rn(o10, o11);
            *(half2*)dst1 = h1;
            float2 f1 = __half22float2(h1);
            *(half2*)(dst1 + 256) = __floats2half2_rn(o10 - f1.x, o11 - f1.y);
        }
    }
}

// ---------------------------------------------------------------------------
// Launch
// ---------------------------------------------------------------------------
extern "C" void kernel_launch(void* const* d_in, const int* in_sizes, int n_in,
                              void* d_out, int out_size)
{
    const float* x       = (const float*)d_in[0];
    const float* q_extra = (const float*)d_in[1];
    const float* kv_w    = (const float*)d_in[2];
    const float* kv_b    = (const float*)d_in[3];
    const float* rpb     = (const float*)d_in[4];
    const float* proj_w  = (const float*)d_in[5];
    const float* proj_b  = (const float*)d_in[6];
    float* out = (float*)d_out;

    h16 *kv_ptr = nullptr, *x2_ptr = nullptr, *att2_ptr = nullptr;
    h16 *w2_ptr = nullptr, *pw2_ptr = nullptr;
    cudaGetSymbolAddress((void**)&kv_ptr,   g_kv);
    cudaGetSymbolAddress((void**)&x2_ptr,   g_x2);
    cudaGetSymbolAddress((void**)&att2_ptr, g_att2);
    cudaGetSymbolAddress((void**)&w2_ptr,   g_w2);
    cudaGetSymbolAddress((void**)&pw2_ptr,  g_pw2);

    const int smem128 = 4 * (128 + 128) * 80;   // 81920
    const int smem64  = 4 * (128 + 64)  * 80;   // 61440
    cudaFuncSetAttribute(gemm_f16<128, 1>,
                         cudaFuncAttributeMaxDynamicSharedMemorySize, smem128);
    cudaFuncSetAttribute(gemm_f16<64, 0>,
                         cudaFuncAttributeMaxDynamicSharedMemorySize, smem64);
    cudaFuncSetAttribute(natt_mma_kernel,
                         cudaFuncAttributeMaxDynamicSharedMemorySize, NATT_SMEM);

    // 0) fused split: fp32 -> 2-term fp16 (x, kv_w, proj_w)
    split_all_kernel<<<(NSPLIT / 2 + 255) / 256, 256>>>(
        x, kv_w, proj_w, x2_ptr, w2_ptr, pw2_ptr);

    // 1) kv = x @ kv_w^T + kv_b   (fp16 output)
    gemm_f16<128, 1><<<dim3(KV_N / 128, NPIX / 128), 256, smem128>>>(
        x2_ptr, w2_ptr, kv_b, kv_ptr, NPIX, KV_N);

    // 2) tensor-core neighborhood attention: 8x8 tiles -> grid (49, 8, 2)
    natt_mma_kernel<<<dim3(49, HEADS, BB), 256, NATT_SMEM>>>(q_extra, rpb);

    // 3) out = att @ proj_w^T + proj_b   (fp32 output)
    gemm_f16<64, 0><<<dim3(CC / 64, NPIX / 128), 256, smem64>>>(
        att2_ptr, pw2_ptr, proj_b, out, NPIX, CC);
}

// round 15
// speedup vs baseline: 1.8375x; 1.0710x over previous
#include <cuda_runtime.h>
#include <cuda_fp16.h>
#include <cstdint>

// Problem constants
#define BB 2
#define HH 56
#define WW 56
#define CC 256
#define HEADS 8
#define NPIX (BB*HH*WW)          // 6272
#define KV_N 512
#define RPB_S 13
#define K2 512                   // 2 * CC (split-fp16 K dimension)

typedef __half h16;

// Scratch (no cudaMalloc allowed)
__device__ h16 g_kv  [NPIX * KV_N];   // fp16: key c[0:256], val c[256:512]
__device__ h16 g_x2  [NPIX * K2];     // [xh, xl]
__device__ h16 g_att2[NPIX * K2];     // [ah, al]
__device__ h16 g_w2  [KV_N * K2];     // [wh, wh]
__device__ h16 g_pw2 [CC   * K2];     // [wh, wh]

// ---------------------------------------------------------------------------
// PTX helpers (scalar args only)
// ---------------------------------------------------------------------------
__device__ __forceinline__ void cp_async16(unsigned dst, const void* src)
{
    asm volatile("cp.async.cg.shared.global [%0], [%1], 16;"
                 :: "r"(dst), "l"(src));
}
__device__ __forceinline__ void cp_commit()
{
    asm volatile("cp.async.commit_group;");
}
__device__ __forceinline__ void cp_wait2()
{
    asm volatile("cp.async.wait_group 2;");
}
__device__ __forceinline__ void cp_wait1()
{
    asm volatile("cp.async.wait_group 1;");
}
__device__ __forceinline__ void cp_wait0()
{
    asm volatile("cp.async.wait_group 0;");
}
__device__ __forceinline__ void ldmx4(uint32_t& r0, uint32_t& r1,
                                      uint32_t& r2, uint32_t& r3, unsigned addr)
{
    asm volatile("ldmatrix.sync.aligned.m8n8.x4.shared.b16 {%0,%1,%2,%3}, [%4];"
                 : "=r"(r0), "=r"(r1), "=r"(r2), "=r"(r3) : "r"(addr));
}
__device__ __forceinline__ void ldmx4t(uint32_t& r0, uint32_t& r1,
                                       uint32_t& r2, uint32_t& r3, unsigned addr)
{
    asm volatile("ldmatrix.sync.aligned.m8n8.x4.trans.shared.b16 {%0,%1,%2,%3}, [%4];"
                 : "=r"(r0), "=r"(r1), "=r"(r2), "=r"(r3) : "r"(addr));
}
__device__ __forceinline__ void mma16816(float& d0, float& d1, float& d2, float& d3,
                                         uint32_t a0, uint32_t a1, uint32_t a2, uint32_t a3,
                                         uint32_t b0, uint32_t b1)
{
    asm volatile("mma.sync.aligned.m16n8k16.row.col.f32.f16.f16.f32 "
                 "{%0,%1,%2,%3}, {%4,%5,%6,%7}, {%8,%9}, {%0,%1,%2,%3};"
                 : "+f"(d0), "+f"(d1), "+f"(d2), "+f"(d3)
                 : "r"(a0), "r"(a1), "r"(a2), "r"(a3), "r"(b0), "r"(b1));
}

// ---------------------------------------------------------------------------
// fused split (vectorized, 2 cols/thread):
// fp32 [rows][256] -> fp16 [rows][512] for x, kv_w, proj_w.
// ---------------------------------------------------------------------------
#define NX (NPIX * CC)
#define NW (KV_N * CC)
#define NPW (CC * CC)
#define NSPLIT (NX + NW + NPW)

__global__ void split_all_kernel(const float* __restrict__ x,
                                 const float* __restrict__ kv_w,
                                 const float* __restrict__ proj_w,
                                 h16* __restrict__ x2,
                                 h16* __restrict__ w2,
                                 h16* __restrict__ pw2)
{
    int idx = blockIdx.x * 256 + threadIdx.x;
    if (idx >= NSPLIT / 2) return;
    int e = idx * 2;

    const float* src;
    h16* dst;
    int actside;
    if (e < NX)            { src = x;      dst = x2;  actside = 1; }
    else if (e < NX + NW)  { e -= NX;  src = kv_w;   dst = w2;  actside = 0; }
    else                   { e -= NX + NW; src = proj_w; dst = pw2; actside = 0; }

    int row = e >> 8, col = e & 255;
    float2 v = *(const float2*)&src[e];
    half2 hi = __floats2half2_rn(v.x, v.y);
    h16* dp = dst + (size_t)row * K2 + col;
    *(half2*)dp = hi;
    if (actside) {
        float2 f = __half22float2(hi);
        *(half2*)(dp + 256) = __floats2half2_rn(v.x - f.x, v.y - f.y);
    } else {
        *(half2*)(dp + 256) = hi;
    }
}

// ---------------------------------------------------------------------------
// fp16 tensor-core GEMM: C[M,N] = A2[M,512] @ B2[N,512]^T + bias
// OUTH=1 -> h16 output, OUTH=0 -> fp32 output.
// ---------------------------------------------------------------------------
template<int BN, int OUTH>
__global__ void __launch_bounds__(256, 2)
gemm_f16(const h16* __restrict__ Amat, const h16* __restrict__ Bmat,
         const float* __restrict__ bias, void* __restrict__ Cmat,
         int Mdim, int Ndim)
{
    constexpr int NT = BN / 32;
    constexpr int NP = BN / 64;
    constexpr unsigned STAGE = (128 + BN) * 80;

    extern __shared__ __align__(16) char smraw[];
    const unsigned smem0 = (unsigned)__cvta_generic_to_shared(smraw);

    const int tid  = threadIdx.x;
    const int lane = tid & 31;
    const int wrp  = tid >> 5;
    const int wm   = wrp & 1;
    const int wn   = wrp >> 1;
    const int m0   = blockIdx.y * 128;
    const int n0   = blockIdx.x * BN;

    const int rr = tid >> 2;
    const int qq = tid & 3;
    const h16* gA0 = Amat + (size_t)(m0 + rr) * K2 + qq * 8;
    const h16* gA1 = gA0 + (size_t)64 * K2;
    const h16* gB0 = Bmat + (size_t)(n0 + rr) * K2 + qq * 8;
    const h16* gB1 = gB0 + (size_t)64 * K2;
    const unsigned sA0 = smem0 + rr * 80 + qq * 16;
    const unsigned sA1 = sA0 + 5120;
    const unsigned sB0 = sA0 + 10240;
    const unsigned sB1 = sB0 + 5120;

    const unsigned almb = smem0 +
        (unsigned)((wm * 64 + (lane & 15)) * 80 + (lane >> 4) * 16);
    const unsigned blmb = smem0 + 10240u +
        (unsigned)((wn * (BN / 4) + (lane & 7) + ((lane >> 4) << 3)) * 80
                   + ((lane >> 3) & 1) * 16);

    float acc[4][NT][4];
#pragma unroll
    for (int mt = 0; mt < 4; mt++)
#pragma unroll
        for (int nt = 0; nt < NT; nt++)
#pragma unroll
            for (int e = 0; e < 4; e++) acc[mt][nt][e] = 0.0f;

#pragma unroll
    for (int st = 0; st < 3; st++) {
        unsigned off = (unsigned)st * STAGE;
        cp_async16(sA0 + off, gA0 + st * 32);
        cp_async16(sA1 + off, gA1 + st * 32);
        cp_async16(sB0 + off, gB0 + st * 32);
        if (BN == 128) cp_async16(sB1 + off, gB1 + st * 32);
        cp_commit();
    }

    const int T = K2 / 32;
    for (int t = 0; t < T; t++) {
        if (t < T - 2) cp_wait2();
        else           cp_wait0();
        __syncthreads();

        if (t + 3 < T) {
            const unsigned off = (unsigned)((t + 3) & 3) * STAGE;
            const int kt = t + 3;
            cp_async16(sA0 + off, gA0 + kt * 32);
            cp_async16(sA1 + off, gA1 + kt * 32);
            cp_async16(sB0 + off, gB0 + kt * 32);
            if (BN == 128) cp_async16(sB1 + off, gB1 + kt * 32);
            cp_commit();
        }

        const unsigned so = (unsigned)(t & 3) * STAGE;
#pragma unroll
        for (int ks = 0; ks < 2; ks++) {
            uint32_t afr[4][4];
            uint32_t bfr[NP][4];
#pragma unroll
            for (int mt = 0; mt < 4; mt++)
                ldmx4(afr[mt][0], afr[mt][1], afr[mt][2], afr[mt][3],
                      almb + so + mt * 1280 + ks * 32);
#pragma unroll
            for (int np = 0; np < NP; np++)
                ldmx4(bfr[np][0], bfr[np][1], bfr[np][2], bfr[np][3],
                      blmb + so + np * 1280 + ks * 32);
#pragma unroll
            for (int mt = 0; mt < 4; mt++) {
#pragma unroll
                for (int nt = 0; nt < NT; nt++) {
                    mma16816(acc[mt][nt][0], acc[mt][nt][1],
                             acc[mt][nt][2], acc[mt][nt][3],
                             afr[mt][0], afr[mt][1], afr[mt][2], afr[mt][3],
                             bfr[nt >> 1][(nt & 1) * 2],
                             bfr[nt >> 1][(nt & 1) * 2 + 1]);
                }
            }
        }
    }

    float2 bv[NT];
#pragma unroll
    for (int nt = 0; nt < NT; nt++)
        bv[nt] = *(const float2*)&bias[n0 + wn * (BN / 4) + nt * 8 + (lane & 3) * 2];

#pragma unroll
    for (int mt = 0; mt < 4; mt++) {
        const int row = m0 + wm * 64 + mt * 16 + (lane >> 2);
#pragma unroll
        for (int nt = 0; nt < NT; nt++) {
            const int col = n0 + wn * (BN / 4) + nt * 8 + (lane & 3) * 2;
            float v00 = acc[mt][nt][0] + bv[nt].x;
            float v01 = acc[mt][nt][1] + bv[nt].y;
            float v10 = acc[mt][nt][2] + bv[nt].x;
            float v11 = acc[mt][nt][3] + bv[nt].y;
            if (OUTH) {
                h16* Cm = (h16*)Cmat;
                *(half2*)&Cm[(size_t)row * Ndim + col]       = __floats2half2_rn(v00, v01);
                *(half2*)&Cm[(size_t)(row + 8) * Ndim + col] = __floats2half2_rn(v10, v11);
            } else {
                float* Cf = (float*)Cmat;
                *(float2*)&Cf[(size_t)row * Ndim + col]       = make_float2(v00, v01);
                *(float2*)&Cf[(size_t)(row + 8) * Ndim + col] = make_float2(v10, v11);
            }
        }
    }
}

// ---------------------------------------------------------------------------
// Tensor-core neighborhood attention, v4 (async staging):
//  - K and V staged via cp.async in two commit groups; Q conversion, rpb,
//    and mask constants overlap the copies. wait_group 1 gates QK (V still
//    in flight through the whole QK+exp phase); wait_group 0 gates AV.
//  - V row-major; AV B-operand via ldmatrix.trans. V dim 32 = 1 -> z col.
//  - 208 padded columns (13 k16-tiles); warps 0-4 take 2 QK tiles, 5-7 one.
// Block = (8x8 pixel tile, head, batch); 2 CTAs/SM.
// ---------------------------------------------------------------------------
#define SM_Q  0        // 64 x 80B   = 5120
#define SM_K  5120     // 208 x 80B  = 16640
#define SM_V  21760    // 212 x 80B  = 16960
#define SM_P  38720    // 64 x 432B  = 27648
#define SM_RS 66368    // 169 x 4B
#define SM_ZS 67048    // 64 x 4B
#define NATT_SMEM 67312

// mask + bias + exp with hoisted row constants
__device__ __forceinline__ float nat_e(float s, int wr, int wc, int ct,
                                       int ar, int jc, int rb,
                                       const float* __restrict__ rs)
{
    if ((unsigned)(wr - ar) < 7u && (unsigned)(wc - jc) < 7u)
        return __expf(s + rs[rb + ct]);
    return 0.0f;
}

__global__ void __launch_bounds__(256, 2)
natt_mma_kernel(const float* __restrict__ q_extra,
                const float* __restrict__ rpb)
{
    extern __shared__ __align__(16) char smraw[];
    const unsigned sm0 = (unsigned)__cvta_generic_to_shared(smraw);
    float* rs = (float*)(smraw + SM_RS);

    const int tid  = threadIdx.x;
    const int lane = tid & 31;
    const int w    = tid >> 5;
    const int bb   = blockIdx.z;
    const int h    = blockIdx.y;
    const int i0   = (blockIdx.x / 7) * 8;
    const int j0   = (blockIdx.x % 7) * 8;
    const int u0   = min(max(i0 - 3, 0), HH - 14);
    const int v0   = min(max(j0 - 3, 0), WW - 14);
    const float scale = 0.17677669529663687f;

    // ---- async staging: K group, then V group ----
    // K: 196 window pixels x 4 uint4
    for (int idx = tid; idx < 196 * 4; idx += 256) {
        int wp = idx >> 2, c = idx & 3;
        int wr = wp / 14, wc = wp % 14;
        int pix = (bb * HH + u0 + wr) * WW + v0 + wc;
        cp_async16(sm0 + SM_K + wp * 80 + c * 16,
                   g_kv + (size_t)pix * KV_N + h * 32 + c * 8);
    }
    cp_commit();   // group K
    // V: 196 window pixels x 4 uint4 (value block = +256 h16)
    for (int idx = tid; idx < 196 * 4; idx += 256) {
        int wp = idx >> 2, c = idx & 3;
        int wr = wp / 14, wc = wp % 14;
        int pix = (bb * HH + u0 + wr) * WW + v0 + wc;
        cp_async16(sm0 + SM_V + wp * 80 + c * 16,
                   g_kv + (size_t)pix * KV_N + 256 + h * 32 + c * 8);
    }
    cp_commit();   // group V

    // ---- overlapped work while copies are in flight ----
    // zero K pad rows 196-207 (12 x 5 uint4)
    if (tid < 60)
        *(uint4*)(smraw + SM_K + (196 + tid / 5) * 80 + (tid % 5) * 16) =
            make_uint4(0, 0, 0, 0);
    // zero V pad rows 196-211 (16 x 5 uint4)
    if (tid >= 60 && tid < 140) {
        int t2 = tid - 60;
        *(uint4*)(smraw + SM_V + (196 + t2 / 5) * 80 + (t2 % 5) * 16) =
            make_uint4(0, 0, 0, 0);
    }
    // V tail: dim 32 = 1.0 (z column), dims 33-39 = 0
    for (int idx = tid; idx < 196; idx += 256)
        *(uint4*)(smraw + SM_V + idx * 80 + 64) = make_uint4(0x3C00u, 0, 0, 0);

    // rpb slice
    for (int idx = tid; idx < RPB_S * RPB_S; idx += 256)
        rs[idx] = rpb[h * RPB_S * RPB_S + idx];

    // Q: 64 tasks x 32 dims fp32 -> fp16 * scale
    for (int idx = tid; idx < 512; idx += 256) {
        int task = idx >> 3, c4 = idx & 7;
        int ii = i0 + (task >> 3), jj = j0 + (task & 7);
        int pix = (bb * HH + ii) * WW + jj;
        float4 v = *(const float4*)&q_extra[(size_t)pix * CC + h * 32 + c4 * 4];
        half2* dq = (half2*)(smraw + SM_Q + task * 80 + c4 * 8);
        dq[0] = __floats2half2_rn(v.x * scale, v.y * scale);
        dq[1] = __floats2half2_rn(v.z * scale, v.w * scale);
    }

    // per-thread row constants (8 rows: [half][mt]) — pure ALU, overlaps copies
    int rowar[2][4], rowjc[2][4], rowbias[2][4];
#pragma unroll
    for (int hf = 0; hf < 2; hf++) {
#pragma unroll
        for (int mt = 0; mt < 4; mt++) {
            const int row = mt * 16 + (lane >> 2) + hf * 8;
            const int ii = i0 + (row >> 3), jj = j0 + (row & 7);
            const int ar  = min(max(ii - 3, 0), HH - 7) - u0;
            const int pis = 3 + max(3 - ii, 0) + min(HH - 4 - ii, 0);
            const int jc  = min(max(jj - 3, 0), WW - 7) - v0;
            const int pjs = 3 + max(3 - jj, 0) + min(WW - 4 - jj, 0);
            rowar[hf][mt]   = ar;
            rowjc[hf][mt]   = jc;
            rowbias[hf][mt] = (pis - ar) * RPB_S + (pjs - jc);
        }
    }

    // K ready (V may still be in flight); Q/rpb staged by all threads
    cp_wait1();
    __syncthreads();

    // ---- QK phase: warp w owns tile w, and tile w+8 if w < 5 ----
    uint32_t afr[4][2][4];
#pragma unroll
    for (int mt = 0; mt < 4; mt++)
#pragma unroll
        for (int ks = 0; ks < 2; ks++)
            ldmx4(afr[mt][ks][0], afr[mt][ks][1], afr[mt][ks][2], afr[mt][ks][3],
                  sm0 + SM_Q + (mt * 16 + (lane & 15)) * 80 + (lane >> 4) * 16 + ks * 32);

    const int cq = (lane & 3) * 2;
#pragma unroll
    for (int pi = 0; pi < 2; pi++) {
        if (pi == 1 && w >= 5) break;      // uniform per warp
        const int p = w + pi * 8;          // column k16-tile index (0..12)
        float qc0[4][4], qc1[4][4];
#pragma unroll
        for (int mt = 0; mt < 4; mt++)
#pragma unroll
            for (int e = 0; e < 4; e++) { qc0[mt][e] = 0.0f; qc1[mt][e] = 0.0f; }

#pragma unroll
        for (int ks = 0; ks < 2; ks++) {
            uint32_t bf[4];
            ldmx4(bf[0], bf[1], bf[2], bf[3],
                  sm0 + SM_K + (p * 16 + (lane & 7) + ((lane >> 4) << 3)) * 80
                  + ((lane >> 3) & 1) * 16 + ks * 32);
#pragma unroll
            for (int mt = 0; mt < 4; mt++) {
                mma16816(qc0[mt][0], qc0[mt][1], qc0[mt][2], qc0[mt][3],
                         afr[mt][ks][0], afr[mt][ks][1], afr[mt][ks][2], afr[mt][ks][3],
                         bf[0], bf[1]);
                mma16816(qc1[mt][0], qc1[mt][1], qc1[mt][2], qc1[mt][3],
                         afr[mt][ks][0], afr[mt][ks][1], afr[mt][ks][2], afr[mt][ks][3],
                         bf[2], bf[3]);
            }
        }

        // bias + mask + exp -> P (fp16, unnormalized)
#pragma unroll
        for (int grp = 0; grp < 2; grp++) {
            const int c0  = p * 16 + grp * 8 + cq;
            const int c1  = c0 + 1;
            const int wr0 = (c0 * 4682) >> 16;
            const int wc0 = c0 - wr0 * 14;
            const int wr1 = (c1 * 4682) >> 16;
            const int wc1 = c1 - wr1 * 14;
            const int ct0 = wr0 * RPB_S + wc0;
            const int ct1 = wr1 * RPB_S + wc1;
#pragma unroll
            for (int mt = 0; mt < 4; mt++) {
                const int r0 = mt * 16 + (lane >> 2);
                float s00 = grp ? qc1[mt][0] : qc0[mt][0];
                float s01 = grp ? qc1[mt][1] : qc0[mt][1];
                float s10 = grp ? qc1[mt][2] : qc0[mt][2];
                float s11 = grp ? qc1[mt][3] : qc0[mt][3];
                float e00 = nat_e(s00, wr0, wc0, ct0, rowar[0][mt], rowjc[0][mt], rowbias[0][mt], rs);
                float e01 = nat_e(s01, wr1, wc1, ct1, rowar[0][mt], rowjc[0][mt], rowbias[0][mt], rs);
                float e10 = nat_e(s10, wr0, wc0, ct0, rowar[1][mt], rowjc[1][mt], rowbias[1][mt], rs);
                float e11 = nat_e(s11, wr1, wc1, ct1, rowar[1][mt], rowjc[1][mt], rowbias[1][mt], rs);
                *(half2*)(smraw + SM_P + r0 * 432 + c0 * 2)       = __floats2half2_rn(e00, e01);
                *(half2*)(smraw + SM_P + (r0 + 8) * 432 + c0 * 2) = __floats2half2_rn(e10, e11);
            }
        }
    }

    // V copies done + P visible to all warps
    cp_wait0();
    __syncthreads();

    // ---- AV phase: O[64x40] = P[64x208] @ V[208x40] (B via ldmatrix.trans) ----
    const int  mtav    = w & 3;
    const bool hi_half = (w >= 4);
    float av[3][4];
#pragma unroll
    for (int u2 = 0; u2 < 3; u2++)
#pragma unroll
        for (int e = 0; e < 4; e++) av[u2][e] = 0.0f;

    const unsigned pa = sm0 + SM_P +
        (mtav * 16 + (lane & 15)) * 432 + (lane >> 4) * 16;
    // trans B: row = k (window pixel), byte col = dim*2
    const unsigned pb = sm0 + SM_V + (lane & 15) * 80 +
        (hi_half ? 32u : 0u) + (lane >> 4) * 16;
    const unsigned pb2 = sm0 + SM_V + (lane & 15) * 80 + 64 + (lane >> 4) * 16;

#pragma unroll
    for (int ks = 0; ks < 13; ks++) {
        uint32_t a4[4], b4[4];
        ldmx4(a4[0], a4[1], a4[2], a4[3], pa + ks * 32);
        ldmx4t(b4[0], b4[1], b4[2], b4[3], pb + ks * 1280);
        mma16816(av[0][0], av[0][1], av[0][2], av[0][3],
                 a4[0], a4[1], a4[2], a4[3], b4[0], b4[1]);
        mma16816(av[1][0], av[1][1], av[1][2], av[1][3],
                 a4[0], a4[1], a4[2], a4[3], b4[2], b4[3]);
        if (hi_half) {
            uint32_t b2[4];
            ldmx4t(b2[0], b2[1], b2[2], b2[3], pb2 + ks * 1280);
            mma16816(av[2][0], av[2][1], av[2][2], av[2][3],
                     a4[0], a4[1], a4[2], a4[3], b2[0], b2[1]);
        }
    }

    // z (col 32) -> smem
    if (hi_half && (lane & 3) == 0) {
        const int r0 = mtav * 16 + (lane >> 2);
        *(float*)(smraw + SM_ZS + r0 * 4)       = av[2][0];
        *(float*)(smraw + SM_ZS + (r0 + 8) * 4) = av[2][2];
    }
    __syncthreads();

    // ---- normalize + store split-fp16 ----
    {
        const int r0 = mtav * 16 + (lane >> 2);
        const float zi0 = __frcp_rn(*(float*)(smraw + SM_ZS + r0 * 4));
        const float zi1 = __frcp_rn(*(float*)(smraw + SM_ZS + (r0 + 8) * 4));
        const int pix0 = (bb * HH + i0 + (r0 >> 3)) * WW + j0 + (r0 & 7);
        const int pix1 = (bb * HH + i0 + (r0 >> 3) + 1) * WW + j0 + (r0 & 7);
#pragma unroll
        for (int nti = 0; nti < 2; nti++) {
            const int d0 = (hi_half ? 16 : 0) + nti * 8 + (lane & 3) * 2;
            float o00 = av[nti][0] * zi0, o01 = av[nti][1] * zi0;
            float o10 = av[nti][2] * zi1, o11 = av[nti][3] * zi1;

            h16* dst0 = g_att2 + (size_t)pix0 * K2 + h * 32 + d0;
            half2 h0 = __floats2half2_rn(o00, o01);
            *(half2*)dst0 = h0;
            float2 f0 = __half22float2(h0);
            *(half2*)(dst0 + 256) = __floats2half2_rn(o00 - f0.x, o01 - f0.y);

            h16* dst1 = g_att2 + (size_t)pix1 * K2 + h * 32 + d0;
            half2 h1 = __floats2half2_rn(o10, o11);
            *(half2*)dst1 = h1;
            float2 f1 = __half22float2(h1);
            *(half2*)(dst1 + 256) = __floats2half2_rn(o10 - f1.x, o11 - f1.y);
        }
    }
}

// ---------------------------------------------------------------------------
// Launch
// ---------------------------------------------------------------------------
extern "C" void kernel_launch(void* const* d_in, const int* in_sizes, int n_in,
                              void* d_out, int out_size)
{
    const float* x       = (const float*)d_in[0];
    const float* q_extra = (const float*)d_in[1];
    const float* kv_w    = (const float*)d_in[2];
    const float* kv_b    = (const float*)d_in[3];
    const float* rpb     = (const float*)d_in[4];
    const float* proj_w  = (const float*)d_in[5];
    const float* proj_b  = (const float*)d_in[6];
    float* out = (float*)d_out;

    h16 *kv_ptr = nullptr, *x2_ptr = nullptr, *att2_ptr = nullptr;
    h16 *w2_ptr = nullptr, *pw2_ptr = nullptr;
    cudaGetSymbolAddress((void**)&kv_ptr,   g_kv);
    cudaGetSymbolAddress((void**)&x2_ptr,   g_x2);
    cudaGetSymbolAddress((void**)&att2_ptr, g_att2);
    cudaGetSymbolAddress((void**)&w2_ptr,   g_w2);
    cudaGetSymbolAddress((void**)&pw2_ptr,  g_pw2);

    const int smem128 = 4 * (128 + 128) * 80;   // 81920
    const int smem64  = 4 * (128 + 64)  * 80;   // 61440
    cudaFuncSetAttribute(gemm_f16<128, 1>,
                         cudaFuncAttributeMaxDynamicSharedMemorySize, smem128);
    cudaFuncSetAttribute(gemm_f16<64, 0>,
                         cudaFuncAttributeMaxDynamicSharedMemorySize, smem64);
    cudaFuncSetAttribute(natt_mma_kernel,
                         cudaFuncAttributeMaxDynamicSharedMemorySize, NATT_SMEM);

    // 0) fused split: fp32 -> 2-term fp16 (x, kv_w, proj_w)
    split_all_kernel<<<(NSPLIT / 2 + 255) / 256, 256>>>(
        x, kv_w, proj_w, x2_ptr, w2_ptr, pw2_ptr);

    // 1) kv = x @ kv_w^T + kv_b   (fp16 output)
    gemm_f16<128, 1><<<dim3(KV_N / 128, NPIX / 128), 256, smem128>>>(
        x2_ptr, w2_ptr, kv_b, kv_ptr, NPIX, KV_N);

    // 2) tensor-core neighborhood attention: 8x8 tiles -> grid (49, 8, 2)
    natt_mma_kernel<<<dim3(49, HEADS, BB), 256, NATT_SMEM>>>(q_extra, rpb);

    // 3) out = att @ proj_w^T + proj_b   (fp32 output)
    gemm_f16<64, 0><<<dim3(CC / 64, NPIX / 128), 256, smem64>>>(
        att2_ptr, pw2_ptr, proj_b, out, NPIX, CC);
}

// round 16
// speedup vs baseline: 2.3871x; 1.2991x over previous
#include <cuda_runtime.h>
#include <cuda_fp16.h>
#include <cstdint>

// Problem constants
#define BB 2
#define HH 56
#define WW 56
#define CC 256
#define HEADS 8
#define NPIX (BB*HH*WW)          // 6272
#define KV_N 512
#define RPB_S 13
#define K1 256                   // plain fp16 K dimension

typedef __half h16;

// Scratch (no cudaMalloc allowed)
__device__ h16 g_kv  [NPIX * KV_N];   // fp16: key c[0:256], val c[256:512]
__device__ h16 g_x1  [NPIX * CC];
__device__ h16 g_att1[NPIX * CC];
__device__ h16 g_w1  [KV_N * CC];
__device__ h16 g_pw1 [CC   * CC];

// ---------------------------------------------------------------------------
// PTX helpers (scalar args only)
// ---------------------------------------------------------------------------
__device__ __forceinline__ void cp_async16(unsigned dst, const void* src)
{
    asm volatile("cp.async.cg.shared.global [%0], [%1], 16;"
                 :: "r"(dst), "l"(src));
}
__device__ __forceinline__ void cp_commit()
{
    asm volatile("cp.async.commit_group;");
}
__device__ __forceinline__ void cp_wait2()
{
    asm volatile("cp.async.wait_group 2;");
}
__device__ __forceinline__ void cp_wait1()
{
    asm volatile("cp.async.wait_group 1;");
}
__device__ __forceinline__ void cp_wait0()
{
    asm volatile("cp.async.wait_group 0;");
}
__device__ __forceinline__ void ldmx4(uint32_t& r0, uint32_t& r1,
                                      uint32_t& r2, uint32_t& r3, unsigned addr)
{
    asm volatile("ldmatrix.sync.aligned.m8n8.x4.shared.b16 {%0,%1,%2,%3}, [%4];"
                 : "=r"(r0), "=r"(r1), "=r"(r2), "=r"(r3) : "r"(addr));
}
__device__ __forceinline__ void ldmx4t(uint32_t& r0, uint32_t& r1,
                                       uint32_t& r2, uint32_t& r3, unsigned addr)
{
    asm volatile("ldmatrix.sync.aligned.m8n8.x4.trans.shared.b16 {%0,%1,%2,%3}, [%4];"
                 : "=r"(r0), "=r"(r1), "=r"(r2), "=r"(r3) : "r"(addr));
}
__device__ __forceinline__ void mma16816(float& d0, float& d1, float& d2, float& d3,
                                         uint32_t a0, uint32_t a1, uint32_t a2, uint32_t a3,
                                         uint32_t b0, uint32_t b1)
{
    asm volatile("mma.sync.aligned.m16n8k16.row.col.f32.f16.f16.f32 "
                 "{%0,%1,%2,%3}, {%4,%5,%6,%7}, {%8,%9}, {%0,%1,%2,%3};"
                 : "+f"(d0), "+f"(d1), "+f"(d2), "+f"(d3)
                 : "r"(a0), "r"(a1), "r"(a2), "r"(a3), "r"(b0), "r"(b1));
}

// ---------------------------------------------------------------------------
// fused convert: fp32 -> fp16 for x, kv_w, proj_w (2 elems/thread)
// ---------------------------------------------------------------------------
#define NX (NPIX * CC)
#define NW (KV_N * CC)
#define NPW (CC * CC)
#define NSPLIT (NX + NW + NPW)

__global__ void conv_all_kernel(const float* __restrict__ x,
                                const float* __restrict__ kv_w,
                                const float* __restrict__ proj_w,
                                h16* __restrict__ x1,
                                h16* __restrict__ w1,
                                h16* __restrict__ pw1)
{
    int idx = blockIdx.x * 256 + threadIdx.x;
    if (idx >= NSPLIT / 2) return;
    int e = idx * 2;

    const float* src;
    h16* dst;
    if (e < NX)            { src = x;      dst = x1; }
    else if (e < NX + NW)  { e -= NX;      src = kv_w;   dst = w1; }
    else                   { e -= NX + NW; src = proj_w; dst = pw1; }

    float2 v = *(const float2*)&src[e];
    *(half2*)&dst[e] = __floats2half2_rn(v.x, v.y);
}

// ---------------------------------------------------------------------------
// fp16 tensor-core GEMM: C[M,N] = A[M,256] @ B[N,256]^T + bias
// OUTH=1 -> h16 output, OUTH=0 -> fp32 output.
// ---------------------------------------------------------------------------
template<int BN, int OUTH>
__global__ void __launch_bounds__(256, 2)
gemm_f16(const h16* __restrict__ Amat, const h16* __restrict__ Bmat,
         const float* __restrict__ bias, void* __restrict__ Cmat,
         int Mdim, int Ndim)
{
    constexpr int NT = BN / 32;
    constexpr int NP = BN / 64;
    constexpr unsigned STAGE = (128 + BN) * 80;

    extern __shared__ __align__(16) char smraw[];
    const unsigned smem0 = (unsigned)__cvta_generic_to_shared(smraw);

    const int tid  = threadIdx.x;
    const int lane = tid & 31;
    const int wrp  = tid >> 5;
    const int wm   = wrp & 1;
    const int wn   = wrp >> 1;
    const int m0   = blockIdx.y * 128;
    const int n0   = blockIdx.x * BN;

    const int rr = tid >> 2;
    const int qq = tid & 3;
    const h16* gA0 = Amat + (size_t)(m0 + rr) * K1 + qq * 8;
    const h16* gA1 = gA0 + (size_t)64 * K1;
    const h16* gB0 = Bmat + (size_t)(n0 + rr) * K1 + qq * 8;
    const h16* gB1 = gB0 + (size_t)64 * K1;
    const unsigned sA0 = smem0 + rr * 80 + qq * 16;
    const unsigned sA1 = sA0 + 5120;
    const unsigned sB0 = sA0 + 10240;
    const unsigned sB1 = sB0 + 5120;

    const unsigned almb = smem0 +
        (unsigned)((wm * 64 + (lane & 15)) * 80 + (lane >> 4) * 16);
    const unsigned blmb = smem0 + 10240u +
        (unsigned)((wn * (BN / 4) + (lane & 7) + ((lane >> 4) << 3)) * 80
                   + ((lane >> 3) & 1) * 16);

    float acc[4][NT][4];
#pragma unroll
    for (int mt = 0; mt < 4; mt++)
#pragma unroll
        for (int nt = 0; nt < NT; nt++)
#pragma unroll
            for (int e = 0; e < 4; e++) acc[mt][nt][e] = 0.0f;

#pragma unroll
    for (int st = 0; st < 3; st++) {
        unsigned off = (unsigned)st * STAGE;
        cp_async16(sA0 + off, gA0 + st * 32);
        cp_async16(sA1 + off, gA1 + st * 32);
        cp_async16(sB0 + off, gB0 + st * 32);
        if (BN == 128) cp_async16(sB1 + off, gB1 + st * 32);
        cp_commit();
    }

    const int T = K1 / 32;    // 8 k-tiles
    for (int t = 0; t < T; t++) {
        if (t < T - 2) cp_wait2();
        else           cp_wait0();
        __syncthreads();

        if (t + 3 < T) {
            const unsigned off = (unsigned)((t + 3) & 3) * STAGE;
            const int kt = t + 3;
            cp_async16(sA0 + off, gA0 + kt * 32);
            cp_async16(sA1 + off, gA1 + kt * 32);
            cp_async16(sB0 + off, gB0 + kt * 32);
            if (BN == 128) cp_async16(sB1 + off, gB1 + kt * 32);
            cp_commit();
        }

        const unsigned so = (unsigned)(t & 3) * STAGE;
#pragma unroll
        for (int ks = 0; ks < 2; ks++) {
            uint32_t afr[4][4];
            uint32_t bfr[NP][4];
#pragma unroll
            for (int mt = 0; mt < 4; mt++)
                ldmx4(afr[mt][0], afr[mt][1], afr[mt][2], afr[mt][3],
                      almb + so + mt * 1280 + ks * 32);
#pragma unroll
            for (int np = 0; np < NP; np++)
                ldmx4(bfr[np][0], bfr[np][1], bfr[np][2], bfr[np][3],
                      blmb + so + np * 1280 + ks * 32);
#pragma unroll
            for (int mt = 0; mt < 4; mt++) {
#pragma unroll
                for (int nt = 0; nt < NT; nt++) {
                    mma16816(acc[mt][nt][0], acc[mt][nt][1],
                             acc[mt][nt][2], acc[mt][nt][3],
                             afr[mt][0], afr[mt][1], afr[mt][2], afr[mt][3],
                             bfr[nt >> 1][(nt & 1) * 2],
                             bfr[nt >> 1][(nt & 1) * 2 + 1]);
                }
            }
        }
    }

    float2 bv[NT];
#pragma unroll
    for (int nt = 0; nt < NT; nt++)
        bv[nt] = *(const float2*)&bias[n0 + wn * (BN / 4) + nt * 8 + (lane & 3) * 2];

#pragma unroll
    for (int mt = 0; mt < 4; mt++) {
        const int row = m0 + wm * 64 + mt * 16 + (lane >> 2);
#pragma unroll
        for (int nt = 0; nt < NT; nt++) {
            const int col = n0 + wn * (BN / 4) + nt * 8 + (lane & 3) * 2;
            float v00 = acc[mt][nt][0] + bv[nt].x;
            float v01 = acc[mt][nt][1] + bv[nt].y;
            float v10 = acc[mt][nt][2] + bv[nt].x;
            float v11 = acc[mt][nt][3] + bv[nt].y;
            if (OUTH) {
                h16* Cm = (h16*)Cmat;
                *(half2*)&Cm[(size_t)row * Ndim + col]       = __floats2half2_rn(v00, v01);
                *(half2*)&Cm[(size_t)(row + 8) * Ndim + col] = __floats2half2_rn(v10, v11);
            } else {
                float* Cf = (float*)Cmat;
                *(float2*)&Cf[(size_t)row * Ndim + col]       = make_float2(v00, v01);
                *(float2*)&Cf[(size_t)(row + 8) * Ndim + col] = make_float2(v10, v11);
            }
        }
    }
}

// ---------------------------------------------------------------------------
// Tensor-core neighborhood attention (async staging, plain fp16 output).
// ---------------------------------------------------------------------------
#define SM_Q  0        // 64 x 80B   = 5120
#define SM_K  5120     // 208 x 80B  = 16640
#define SM_V  21760    // 212 x 80B  = 16960
#define SM_P  38720    // 64 x 432B  = 27648
#define SM_RS 66368    // 169 x 4B
#define SM_ZS 67048    // 64 x 4B
#define NATT_SMEM 67312

// mask + bias + exp with hoisted row constants
__device__ __forceinline__ float nat_e(float s, int wr, int wc, int ct,
                                       int ar, int jc, int rb,
                                       const float* __restrict__ rs)
{
    if ((unsigned)(wr - ar) < 7u && (unsigned)(wc - jc) < 7u)
        return __expf(s + rs[rb + ct]);
    return 0.0f;
}

__global__ void __launch_bounds__(256, 2)
natt_mma_kernel(const float* __restrict__ q_extra,
                const float* __restrict__ rpb)
{
    extern __shared__ __align__(16) char smraw[];
    const unsigned sm0 = (unsigned)__cvta_generic_to_shared(smraw);
    float* rs = (float*)(smraw + SM_RS);

    const int tid  = threadIdx.x;
    const int lane = tid & 31;
    const int w    = tid >> 5;
    const int bb   = blockIdx.z;
    const int h    = blockIdx.y;
    const int i0   = (blockIdx.x / 7) * 8;
    const int j0   = (blockIdx.x % 7) * 8;
    const int u0   = min(max(i0 - 3, 0), HH - 14);
    const int v0   = min(max(j0 - 3, 0), WW - 14);
    const float scale = 0.17677669529663687f;

    // ---- async staging: K group, then V group ----
    for (int idx = tid; idx < 196 * 4; idx += 256) {
        int wp = idx >> 2, c = idx & 3;
        int wr = wp / 14, wc = wp % 14;
        int pix = (bb * HH + u0 + wr) * WW + v0 + wc;
        cp_async16(sm0 + SM_K + wp * 80 + c * 16,
                   g_kv + (size_t)pix * KV_N + h * 32 + c * 8);
    }
    cp_commit();   // group K
    for (int idx = tid; idx < 196 * 4; idx += 256) {
        int wp = idx >> 2, c = idx & 3;
        int wr = wp / 14, wc = wp % 14;
        int pix = (bb * HH + u0 + wr) * WW + v0 + wc;
        cp_async16(sm0 + SM_V + wp * 80 + c * 16,
                   g_kv + (size_t)pix * KV_N + 256 + h * 32 + c * 8);
    }
    cp_commit();   // group V

    // ---- overlapped work while copies are in flight ----
    if (tid < 60)
        *(uint4*)(smraw + SM_K + (196 + tid / 5) * 80 + (tid % 5) * 16) =
            make_uint4(0, 0, 0, 0);
    if (tid >= 60 && tid < 140) {
        int t2 = tid - 60;
        *(uint4*)(smraw + SM_V + (196 + t2 / 5) * 80 + (t2 % 5) * 16) =
            make_uint4(0, 0, 0, 0);
    }
    for (int idx = tid; idx < 196; idx += 256)
        *(uint4*)(smraw + SM_V + idx * 80 + 64) = make_uint4(0x3C00u, 0, 0, 0);

    for (int idx = tid; idx < RPB_S * RPB_S; idx += 256)
        rs[idx] = rpb[h * RPB_S * RPB_S + idx];

    for (int idx = tid; idx < 512; idx += 256) {
        int task = idx >> 3, c4 = idx & 7;
        int ii = i0 + (task >> 3), jj = j0 + (task & 7);
        int pix = (bb * HH + ii) * WW + jj;
        float4 v = *(const float4*)&q_extra[(size_t)pix * CC + h * 32 + c4 * 4];
        half2* dq = (half2*)(smraw + SM_Q + task * 80 + c4 * 8);
        dq[0] = __floats2half2_rn(v.x * scale, v.y * scale);
        dq[1] = __floats2half2_rn(v.z * scale, v.w * scale);
    }

    int rowar[2][4], rowjc[2][4], rowbias[2][4];
#pragma unroll
    for (int hf = 0; hf < 2; hf++) {
#pragma unroll
        for (int mt = 0; mt < 4; mt++) {
            const int row = mt * 16 + (lane >> 2) + hf * 8;
            const int ii = i0 + (row >> 3), jj = j0 + (row & 7);
            const int ar  = min(max(ii - 3, 0), HH - 7) - u0;
            const int pis = 3 + max(3 - ii, 0) + min(HH - 4 - ii, 0);
            const int jc  = min(max(jj - 3, 0), WW - 7) - v0;
            const int pjs = 3 + max(3 - jj, 0) + min(WW - 4 - jj, 0);
            rowar[hf][mt]   = ar;
            rowjc[hf][mt]   = jc;
            rowbias[hf][mt] = (pis - ar) * RPB_S + (pjs - jc);
        }
    }

    cp_wait1();
    __syncthreads();

    // ---- QK phase ----
    uint32_t afr[4][2][4];
#pragma unroll
    for (int mt = 0; mt < 4; mt++)
#pragma unroll
        for (int ks = 0; ks < 2; ks++)
            ldmx4(afr[mt][ks][0], afr[mt][ks][1], afr[mt][ks][2], afr[mt][ks][3],
                  sm0 + SM_Q + (mt * 16 + (lane & 15)) * 80 + (lane >> 4) * 16 + ks * 32);

    const int cq = (lane & 3) * 2;
#pragma unroll
    for (int pi = 0; pi < 2; pi++) {
        if (pi == 1 && w >= 5) break;
        const int p = w + pi * 8;
        float qc0[4][4], qc1[4][4];
#pragma unroll
        for (int mt = 0; mt < 4; mt++)
#pragma unroll
            for (int e = 0; e < 4; e++) { qc0[mt][e] = 0.0f; qc1[mt][e] = 0.0f; }

#pragma unroll
        for (int ks = 0; ks < 2; ks++) {
            uint32_t bf[4];
            ldmx4(bf[0], bf[1], bf[2], bf[3],
                  sm0 + SM_K + (p * 16 + (lane & 7) + ((lane >> 4) << 3)) * 80
                  + ((lane >> 3) & 1) * 16 + ks * 32);
#pragma unroll
            for (int mt = 0; mt < 4; mt++) {
                mma16816(qc0[mt][0], qc0[mt][1], qc0[mt][2], qc0[mt][3],
                         afr[mt][ks][0], afr[mt][ks][1], afr[mt][ks][2], afr[mt][ks][3],
                         bf[0], bf[1]);
                mma16816(qc1[mt][0], qc1[mt][1], qc1[mt][2], qc1[mt][3],
                         afr[mt][ks][0], afr[mt][ks][1], afr[mt][ks][2], afr[mt][ks][3],
                         bf[2], bf[3]);
            }
        }

#pragma unroll
        for (int grp = 0; grp < 2; grp++) {
            const int c0  = p * 16 + grp * 8 + cq;
            const int c1  = c0 + 1;
            const int wr0 = (c0 * 4682) >> 16;
            const int wc0 = c0 - wr0 * 14;
            const int wr1 = (c1 * 4682) >> 16;
            const int wc1 = c1 - wr1 * 14;
            const int ct0 = wr0 * RPB_S + wc0;
            const int ct1 = wr1 * RPB_S + wc1;
#pragma unroll
            for (int mt = 0; mt < 4; mt++) {
                const int r0 = mt * 16 + (lane >> 2);
                float s00 = grp ? qc1[mt][0] : qc0[mt][0];
                float s01 = grp ? qc1[mt][1] : qc0[mt][1];
                float s10 = grp ? qc1[mt][2] : qc0[mt][2];
                float s11 = grp ? qc1[mt][3] : qc0[mt][3];
                float e00 = nat_e(s00, wr0, wc0, ct0, rowar[0][mt], rowjc[0][mt], rowbias[0][mt], rs);
                float e01 = nat_e(s01, wr1, wc1, ct1, rowar[0][mt], rowjc[0][mt], rowbias[0][mt], rs);
                float e10 = nat_e(s10, wr0, wc0, ct0, rowar[1][mt], rowjc[1][mt], rowbias[1][mt], rs);
                float e11 = nat_e(s11, wr1, wc1, ct1, rowar[1][mt], rowjc[1][mt], rowbias[1][mt], rs);
                *(half2*)(smraw + SM_P + r0 * 432 + c0 * 2)       = __floats2half2_rn(e00, e01);
                *(half2*)(smraw + SM_P + (r0 + 8) * 432 + c0 * 2) = __floats2half2_rn(e10, e11);
            }
        }
    }

    cp_wait0();
    __syncthreads();

    // ---- AV phase: O[64x40] = P[64x208] @ V[208x40] (B via ldmatrix.trans) ----
    const int  mtav    = w & 3;
    const bool hi_half = (w >= 4);
    float av[3][4];
#pragma unroll
    for (int u2 = 0; u2 < 3; u2++)
#pragma unroll
        for (int e = 0; e < 4; e++) av[u2][e] = 0.0f;

    const unsigned pa = sm0 + SM_P +
        (mtav * 16 + (lane & 15)) * 432 + (lane >> 4) * 16;
    const unsigned pb = sm0 + SM_V + (lane & 15) * 80 +
        (hi_half ? 32u : 0u) + (lane >> 4) * 16;
    const unsigned pb2 = sm0 + SM_V + (lane & 15) * 80 + 64 + (lane >> 4) * 16;

#pragma unroll
    for (int ks = 0; ks < 13; ks++) {
        uint32_t a4[4], b4[4];
        ldmx4(a4[0], a4[1], a4[2], a4[3], pa + ks * 32);
        ldmx4t(b4[0], b4[1], b4[2], b4[3], pb + ks * 1280);
        mma16816(av[0][0], av[0][1], av[0][2], av[0][3],
                 a4[0], a4[1], a4[2], a4[3], b4[0], b4[1]);
        mma16816(av[1][0], av[1][1], av[1][2], av[1][3],
                 a4[0], a4[1], a4[2], a4[3], b4[2], b4[3]);
        if (hi_half) {
            uint32_t b2[4];
            ldmx4t(b2[0], b2[1], b2[2], b2[3], pb2 + ks * 1280);
            mma16816(av[2][0], av[2][1], av[2][2], av[2][3],
                     a4[0], a4[1], a4[2], a4[3], b2[0], b2[1]);
        }
    }

    if (hi_half && (lane & 3) == 0) {
        const int r0 = mtav * 16 + (lane >> 2);
        *(float*)(smraw + SM_ZS + r0 * 4)       = av[2][0];
        *(float*)(smraw + SM_ZS + (r0 + 8) * 4) = av[2][2];
    }
    __syncthreads();

    // ---- normalize + store fp16 ----
    {
        const int r0 = mtav * 16 + (lane >> 2);
        const float zi0 = __frcp_rn(*(float*)(smraw + SM_ZS + r0 * 4));
        const float zi1 = __frcp_rn(*(float*)(smraw + SM_ZS + (r0 + 8) * 4));
        const int pix0 = (bb * HH + i0 + (r0 >> 3)) * WW + j0 + (r0 & 7);
        const int pix1 = (bb * HH + i0 + (r0 >> 3) + 1) * WW + j0 + (r0 & 7);
#pragma unroll
        for (int nti = 0; nti < 2; nti++) {
            const int d0 = (hi_half ? 16 : 0) + nti * 8 + (lane & 3) * 2;
            *(half2*)&g_att1[(size_t)pix0 * CC + h * 32 + d0] =
                __floats2half2_rn(av[nti][0] * zi0, av[nti][1] * zi0);
            *(half2*)&g_att1[(size_t)pix1 * CC + h * 32 + d0] =
                __floats2half2_rn(av[nti][2] * zi1, av[nti][3] * zi1);
        }
    }
}

// ---------------------------------------------------------------------------
// Launch
// ---------------------------------------------------------------------------
extern "C" void kernel_launch(void* const* d_in, const int* in_sizes, int n_in,
                              void* d_out, int out_size)
{
    const float* x       = (const float*)d_in[0];
    const float* q_extra = (const float*)d_in[1];
    const float* kv_w    = (const float*)d_in[2];
    const float* kv_b    = (const float*)d_in[3];
    const float* rpb     = (const float*)d_in[4];
    const float* proj_w  = (const float*)d_in[5];
    const float* proj_b  = (const float*)d_in[6];
    float* out = (float*)d_out;

    h16 *kv_ptr = nullptr, *x1_ptr = nullptr, *att1_ptr = nullptr;
    h16 *w1_ptr = nullptr, *pw1_ptr = nullptr;
    cudaGetSymbolAddress((void**)&kv_ptr,   g_kv);
    cudaGetSymbolAddress((void**)&x1_ptr,   g_x1);
    cudaGetSymbolAddress((void**)&att1_ptr, g_att1);
    cudaGetSymbolAddress((void**)&w1_ptr,   g_w1);
    cudaGetSymbolAddress((void**)&pw1_ptr,  g_pw1);

    const int smem128 = 4 * (128 + 128) * 80;   // 81920
    const int smem64  = 4 * (128 + 64)  * 80;   // 61440
    cudaFuncSetAttribute(gemm_f16<128, 1>,
                         cudaFuncAttributeMaxDynamicSharedMemorySize, smem128);
    cudaFuncSetAttribute(gemm_f16<64, 0>,
                         cudaFuncAttributeMaxDynamicSharedMemorySize, smem64);
    cudaFuncSetAttribute(natt_mma_kernel,
                         cudaFuncAttributeMaxDynamicSharedMemorySize, NATT_SMEM);

    // 0) convert fp32 -> fp16 (x, kv_w, proj_w)
    conv_all_kernel<<<(NSPLIT / 2 + 255) / 256, 256>>>(
        x, kv_w, proj_w, x1_ptr, w1_ptr, pw1_ptr);

    // 1) kv = x @ kv_w^T + kv_b   (fp16 output, K=256)
    gemm_f16<128, 1><<<dim3(KV_N / 128, NPIX / 128), 256, smem128>>>(
        x1_ptr, w1_ptr, kv_b, kv_ptr, NPIX, KV_N);

    // 2) tensor-core neighborhood attention: 8x8 tiles -> grid (49, 8, 2)
    natt_mma_kernel<<<dim3(49, HEADS, BB), 256, NATT_SMEM>>>(q_extra, rpb);

    // 3) out = att @ proj_w^T + proj_b   (fp32 output, K=256)
    gemm_f16<64, 0><<<dim3(CC / 64, NPIX / 128), 256, smem64>>>(
        att1_ptr, pw1_ptr, proj_b, out, NPIX, CC);
}

// round 17
// speedup vs baseline: 2.3989x; 1.0049x over previous
#include <cuda_runtime.h>
#include <cuda_fp16.h>
#include <cstdint>

// Problem constants
#define BB 2
#define HH 56
#define WW 56
#define CC 256
#define HEADS 8
#define NPIX (BB*HH*WW)          // 6272
#define KV_N 512
#define RPB_S 13
#define K1 256                   // plain fp16 K dimension

typedef __half h16;

// Scratch (no cudaMalloc allowed)
__device__ h16 g_kv  [NPIX * KV_N];   // fp16: key c[0:256], val c[256:512]
__device__ h16 g_x1  [NPIX * CC];
__device__ h16 g_att1[NPIX * CC];
__device__ h16 g_w1  [KV_N * CC];
__device__ h16 g_pw1 [CC   * CC];

// ---------------------------------------------------------------------------
// PTX helpers (scalar args only)
// ---------------------------------------------------------------------------
__device__ __forceinline__ void cp_async16(unsigned dst, const void* src)
{
    asm volatile("cp.async.cg.shared.global [%0], [%1], 16;"
                 :: "r"(dst), "l"(src));
}
__device__ __forceinline__ void cp_commit()
{
    asm volatile("cp.async.commit_group;");
}
__device__ __forceinline__ void cp_wait2()
{
    asm volatile("cp.async.wait_group 2;");
}
__device__ __forceinline__ void cp_wait1()
{
    asm volatile("cp.async.wait_group 1;");
}
__device__ __forceinline__ void cp_wait0()
{
    asm volatile("cp.async.wait_group 0;");
}
__device__ __forceinline__ void ldmx4(uint32_t& r0, uint32_t& r1,
                                      uint32_t& r2, uint32_t& r3, unsigned addr)
{
    asm volatile("ldmatrix.sync.aligned.m8n8.x4.shared.b16 {%0,%1,%2,%3}, [%4];"
                 : "=r"(r0), "=r"(r1), "=r"(r2), "=r"(r3) : "r"(addr));
}
__device__ __forceinline__ void ldmx4t(uint32_t& r0, uint32_t& r1,
                                       uint32_t& r2, uint32_t& r3, unsigned addr)
{
    asm volatile("ldmatrix.sync.aligned.m8n8.x4.trans.shared.b16 {%0,%1,%2,%3}, [%4];"
                 : "=r"(r0), "=r"(r1), "=r"(r2), "=r"(r3) : "r"(addr));
}
__device__ __forceinline__ void mma16816(float& d0, float& d1, float& d2, float& d3,
                                         uint32_t a0, uint32_t a1, uint32_t a2, uint32_t a3,
                                         uint32_t b0, uint32_t b1)
{
    asm volatile("mma.sync.aligned.m16n8k16.row.col.f32.f16.f16.f32 "
                 "{%0,%1,%2,%3}, {%4,%5,%6,%7}, {%8,%9}, {%0,%1,%2,%3};"
                 : "+f"(d0), "+f"(d1), "+f"(d2), "+f"(d3)
                 : "r"(a0), "r"(a1), "r"(a2), "r"(a3), "r"(b0), "r"(b1));
}

// Polynomial exp on the FMA pipe (no MUFU). |s| <= ~10 here.
// exp(s) = 2^n * e^{f ln2}, n = rint(s*log2e), f in [-0.5, 0.5].
// Degree-4 Taylor: max rel err ~4e-5 (invisible under fp16 P quantization).
__device__ __forceinline__ float fast_exp(float s)
{
    float t = s * 1.4426950408889634f;
    float n = rintf(t);
    float f = t - n;
    float p = 0.009618129107628477f;            // (ln2)^4/24
    p = __fmaf_rn(p, f, 0.05550410866482158f);  // (ln2)^3/6
    p = __fmaf_rn(p, f, 0.2402265069591007f);   // (ln2)^2/2
    p = __fmaf_rn(p, f, 0.6931471805599453f);   // ln2
    p = __fmaf_rn(p, f, 1.0f);
    return __int_as_float(__float_as_int(p) + ((int)n << 23));
}

// ---------------------------------------------------------------------------
// fused convert: fp32 -> fp16 for x, kv_w, proj_w (2 elems/thread)
// ---------------------------------------------------------------------------
#define NX (NPIX * CC)
#define NW (KV_N * CC)
#define NPW (CC * CC)
#define NSPLIT (NX + NW + NPW)

__global__ void conv_all_kernel(const float* __restrict__ x,
                                const float* __restrict__ kv_w,
                                const float* __restrict__ proj_w,
                                h16* __restrict__ x1,
                                h16* __restrict__ w1,
                                h16* __restrict__ pw1)
{
    int idx = blockIdx.x * 256 + threadIdx.x;
    if (idx >= NSPLIT / 2) return;
    int e = idx * 2;

    const float* src;
    h16* dst;
    if (e < NX)            { src = x;      dst = x1; }
    else if (e < NX + NW)  { e -= NX;      src = kv_w;   dst = w1; }
    else                   { e -= NX + NW; src = proj_w; dst = pw1; }

    float2 v = *(const float2*)&src[e];
    *(half2*)&dst[e] = __floats2half2_rn(v.x, v.y);
}

// ---------------------------------------------------------------------------
// fp16 tensor-core GEMM: C[M,N] = A[M,256] @ B[N,256]^T + bias
// OUTH=1 -> h16 output, OUTH=0 -> fp32 output.
// ---------------------------------------------------------------------------
template<int BN, int OUTH>
__global__ void __launch_bounds__(256, 2)
gemm_f16(const h16* __restrict__ Amat, const h16* __restrict__ Bmat,
         const float* __restrict__ bias, void* __restrict__ Cmat,
         int Mdim, int Ndim)
{
    constexpr int NT = BN / 32;
    constexpr int NP = BN / 64;
    constexpr unsigned STAGE = (128 + BN) * 80;

    extern __shared__ __align__(16) char smraw[];
    const unsigned smem0 = (unsigned)__cvta_generic_to_shared(smraw);

    const int tid  = threadIdx.x;
    const int lane = tid & 31;
    const int wrp  = tid >> 5;
    const int wm   = wrp & 1;
    const int wn   = wrp >> 1;
    const int m0   = blockIdx.y * 128;
    const int n0   = blockIdx.x * BN;

    const int rr = tid >> 2;
    const int qq = tid & 3;
    const h16* gA0 = Amat + (size_t)(m0 + rr) * K1 + qq * 8;
    const h16* gA1 = gA0 + (size_t)64 * K1;
    const h16* gB0 = Bmat + (size_t)(n0 + rr) * K1 + qq * 8;
    const h16* gB1 = gB0 + (size_t)64 * K1;
    const unsigned sA0 = smem0 + rr * 80 + qq * 16;
    const unsigned sA1 = sA0 + 5120;
    const unsigned sB0 = sA0 + 10240;
    const unsigned sB1 = sB0 + 5120;

    const unsigned almb = smem0 +
        (unsigned)((wm * 64 + (lane & 15)) * 80 + (lane >> 4) * 16);
    const unsigned blmb = smem0 + 10240u +
        (unsigned)((wn * (BN / 4) + (lane & 7) + ((lane >> 4) << 3)) * 80
                   + ((lane >> 3) & 1) * 16);

    float acc[4][NT][4];
#pragma unroll
    for (int mt = 0; mt < 4; mt++)
#pragma unroll
        for (int nt = 0; nt < NT; nt++)
#pragma unroll
            for (int e = 0; e < 4; e++) acc[mt][nt][e] = 0.0f;

#pragma unroll
    for (int st = 0; st < 3; st++) {
        unsigned off = (unsigned)st * STAGE;
        cp_async16(sA0 + off, gA0 + st * 32);
        cp_async16(sA1 + off, gA1 + st * 32);
        cp_async16(sB0 + off, gB0 + st * 32);
        if (BN == 128) cp_async16(sB1 + off, gB1 + st * 32);
        cp_commit();
    }

    const int T = K1 / 32;    // 8 k-tiles
    for (int t = 0; t < T; t++) {
        if (t < T - 2) cp_wait2();
        else           cp_wait0();
        __syncthreads();

        if (t + 3 < T) {
            const unsigned off = (unsigned)((t + 3) & 3) * STAGE;
            const int kt = t + 3;
            cp_async16(sA0 + off, gA0 + kt * 32);
            cp_async16(sA1 + off, gA1 + kt * 32);
            cp_async16(sB0 + off, gB0 + kt * 32);
            if (BN == 128) cp_async16(sB1 + off, gB1 + kt * 32);
            cp_commit();
        }

        const unsigned so = (unsigned)(t & 3) * STAGE;
#pragma unroll
        for (int ks = 0; ks < 2; ks++) {
            uint32_t afr[4][4];
            uint32_t bfr[NP][4];
#pragma unroll
            for (int mt = 0; mt < 4; mt++)
                ldmx4(afr[mt][0], afr[mt][1], afr[mt][2], afr[mt][3],
                      almb + so + mt * 1280 + ks * 32);
#pragma unroll
            for (int np = 0; np < NP; np++)
                ldmx4(bfr[np][0], bfr[np][1], bfr[np][2], bfr[np][3],
                      blmb + so + np * 1280 + ks * 32);
#pragma unroll
            for (int mt = 0; mt < 4; mt++) {
#pragma unroll
                for (int nt = 0; nt < NT; nt++) {
                    mma16816(acc[mt][nt][0], acc[mt][nt][1],
                             acc[mt][nt][2], acc[mt][nt][3],
                             afr[mt][0], afr[mt][1], afr[mt][2], afr[mt][3],
                             bfr[nt >> 1][(nt & 1) * 2],
                             bfr[nt >> 1][(nt & 1) * 2 + 1]);
                }
            }
        }
    }

    float2 bv[NT];
#pragma unroll
    for (int nt = 0; nt < NT; nt++)
        bv[nt] = *(const float2*)&bias[n0 + wn * (BN / 4) + nt * 8 + (lane & 3) * 2];

#pragma unroll
    for (int mt = 0; mt < 4; mt++) {
        const int row = m0 + wm * 64 + mt * 16 + (lane >> 2);
#pragma unroll
        for (int nt = 0; nt < NT; nt++) {
            const int col = n0 + wn * (BN / 4) + nt * 8 + (lane & 3) * 2;
            float v00 = acc[mt][nt][0] + bv[nt].x;
            float v01 = acc[mt][nt][1] + bv[nt].y;
            float v10 = acc[mt][nt][2] + bv[nt].x;
            float v11 = acc[mt][nt][3] + bv[nt].y;
            if (OUTH) {
                h16* Cm = (h16*)Cmat;
                *(half2*)&Cm[(size_t)row * Ndim + col]       = __floats2half2_rn(v00, v01);
                *(half2*)&Cm[(size_t)(row + 8) * Ndim + col] = __floats2half2_rn(v10, v11);
            } else {
                float* Cf = (float*)Cmat;
                *(float2*)&Cf[(size_t)row * Ndim + col]       = make_float2(v00, v01);
                *(float2*)&Cf[(size_t)(row + 8) * Ndim + col] = make_float2(v10, v11);
            }
        }
    }
}

// ---------------------------------------------------------------------------
// Tensor-core neighborhood attention (async staging, FMA-pipe exp).
// ---------------------------------------------------------------------------
#define SM_Q  0        // 64 x 80B   = 5120
#define SM_K  5120     // 208 x 80B  = 16640
#define SM_V  21760    // 212 x 80B  = 16960
#define SM_P  38720    // 64 x 432B  = 27648
#define SM_RS 66368    // 169 x 4B
#define SM_ZS 67048    // 64 x 4B
#define NATT_SMEM 67312

// mask + bias + exp with hoisted row constants
__device__ __forceinline__ float nat_e(float s, int wr, int wc, int ct,
                                       int ar, int jc, int rb,
                                       const float* __restrict__ rs)
{
    if ((unsigned)(wr - ar) < 7u && (unsigned)(wc - jc) < 7u)
        return fast_exp(s + rs[rb + ct]);
    return 0.0f;
}

__global__ void __launch_bounds__(256, 2)
natt_mma_kernel(const float* __restrict__ q_extra,
                const float* __restrict__ rpb)
{
    extern __shared__ __align__(16) char smraw[];
    const unsigned sm0 = (unsigned)__cvta_generic_to_shared(smraw);
    float* rs = (float*)(smraw + SM_RS);

    const int tid  = threadIdx.x;
    const int lane = tid & 31;
    const int w    = tid >> 5;
    const int bb   = blockIdx.z;
    const int h    = blockIdx.y;
    const int i0   = (blockIdx.x / 7) * 8;
    const int j0   = (blockIdx.x % 7) * 8;
    const int u0   = min(max(i0 - 3, 0), HH - 14);
    const int v0   = min(max(j0 - 3, 0), WW - 14);
    const float scale = 0.17677669529663687f;

    // ---- async staging: K group, then V group ----
    for (int idx = tid; idx < 196 * 4; idx += 256) {
        int wp = idx >> 2, c = idx & 3;
        int wr = wp / 14, wc = wp % 14;
        int pix = (bb * HH + u0 + wr) * WW + v0 + wc;
        cp_async16(sm0 + SM_K + wp * 80 + c * 16,
                   g_kv + (size_t)pix * KV_N + h * 32 + c * 8);
    }
    cp_commit();   // group K
    for (int idx = tid; idx < 196 * 4; idx += 256) {
        int wp = idx >> 2, c = idx & 3;
        int wr = wp / 14, wc = wp % 14;
        int pix = (bb * HH + u0 + wr) * WW + v0 + wc;
        cp_async16(sm0 + SM_V + wp * 80 + c * 16,
                   g_kv + (size_t)pix * KV_N + 256 + h * 32 + c * 8);
    }
    cp_commit();   // group V

    // ---- overlapped work while copies are in flight ----
    if (tid < 60)
        *(uint4*)(smraw + SM_K + (196 + tid / 5) * 80 + (tid % 5) * 16) =
            make_uint4(0, 0, 0, 0);
    if (tid >= 60 && tid < 140) {
        int t2 = tid - 60;
        *(uint4*)(smraw + SM_V + (196 + t2 / 5) * 80 + (t2 % 5) * 16) =
            make_uint4(0, 0, 0, 0);
    }
    for (int idx = tid; idx < 196; idx += 256)
        *(uint4*)(smraw + SM_V + idx * 80 + 64) = make_uint4(0x3C00u, 0, 0, 0);

    for (int idx = tid; idx < RPB_S * RPB_S; idx += 256)
        rs[idx] = rpb[h * RPB_S * RPB_S + idx];

    for (int idx = tid; idx < 512; idx += 256) {
        int task = idx >> 3, c4 = idx & 7;
        int ii = i0 + (task >> 3), jj = j0 + (task & 7);
        int pix = (bb * HH + ii) * WW + jj;
        float4 v = *(const float4*)&q_extra[(size_t)pix * CC + h * 32 + c4 * 4];
        half2* dq = (half2*)(smraw + SM_Q + task * 80 + c4 * 8);
        dq[0] = __floats2half2_rn(v.x * scale, v.y * scale);
        dq[1] = __floats2half2_rn(v.z * scale, v.w * scale);
    }

    int rowar[2][4], rowjc[2][4], rowbias[2][4];
#pragma unroll
    for (int hf = 0; hf < 2; hf++) {
#pragma unroll
        for (int mt = 0; mt < 4; mt++) {
            const int row = mt * 16 + (lane >> 2) + hf * 8;
            const int ii = i0 + (row >> 3), jj = j0 + (row & 7);
            const int ar  = min(max(ii - 3, 0), HH - 7) - u0;
            const int pis = 3 + max(3 - ii, 0) + min(HH - 4 - ii, 0);
            const int jc  = min(max(jj - 3, 0), WW - 7) - v0;
            const int pjs = 3 + max(3 - jj, 0) + min(WW - 4 - jj, 0);
            rowar[hf][mt]   = ar;
            rowjc[hf][mt]   = jc;
            rowbias[hf][mt] = (pis - ar) * RPB_S + (pjs - jc);
        }
    }

    cp_wait1();
    __syncthreads();

    // ---- QK phase ----
    uint32_t afr[4][2][4];
#pragma unroll
    for (int mt = 0; mt < 4; mt++)
#pragma unroll
        for (int ks = 0; ks < 2; ks++)
            ldmx4(afr[mt][ks][0], afr[mt][ks][1], afr[mt][ks][2], afr[mt][ks][3],
                  sm0 + SM_Q + (mt * 16 + (lane & 15)) * 80 + (lane >> 4) * 16 + ks * 32);

    const int cq = (lane & 3) * 2;
#pragma unroll
    for (int pi = 0; pi < 2; pi++) {
        if (pi == 1 && w >= 5) break;
        const int p = w + pi * 8;
        float qc0[4][4], qc1[4][4];
#pragma unroll
        for (int mt = 0; mt < 4; mt++)
#pragma unroll
            for (int e = 0; e < 4; e++) { qc0[mt][e] = 0.0f; qc1[mt][e] = 0.0f; }

#pragma unroll
        for (int ks = 0; ks < 2; ks++) {
            uint32_t bf[4];
            ldmx4(bf[0], bf[1], bf[2], bf[3],
                  sm0 + SM_K + (p * 16 + (lane & 7) + ((lane >> 4) << 3)) * 80
                  + ((lane >> 3) & 1) * 16 + ks * 32);
#pragma unroll
            for (int mt = 0; mt < 4; mt++) {
                mma16816(qc0[mt][0], qc0[mt][1], qc0[mt][2], qc0[mt][3],
                         afr[mt][ks][0], afr[mt][ks][1], afr[mt][ks][2], afr[mt][ks][3],
                         bf[0], bf[1]);
                mma16816(qc1[mt][0], qc1[mt][1], qc1[mt][2], qc1[mt][3],
                         afr[mt][ks][0], afr[mt][ks][1], afr[mt][ks][2], afr[mt][ks][3],
                         bf[2], bf[3]);
            }
        }

#pragma unroll
        for (int grp = 0; grp < 2; grp++) {
            const int c0  = p * 16 + grp * 8 + cq;
            const int c1  = c0 + 1;
            const int wr0 = (c0 * 4682) >> 16;
            const int wc0 = c0 - wr0 * 14;
            const int wr1 = (c1 * 4682) >> 16;
            const int wc1 = c1 - wr1 * 14;
            const int ct0 = wr0 * RPB_S + wc0;
            const int ct1 = wr1 * RPB_S + wc1;
#pragma unroll
            for (int mt = 0; mt < 4; mt++) {
                const int r0 = mt * 16 + (lane >> 2);
                float s00 = grp ? qc1[mt][0] : qc0[mt][0];
                float s01 = grp ? qc1[mt][1] : qc0[mt][1];
                float s10 = grp ? qc1[mt][2] : qc0[mt][2];
                float s11 = grp ? qc1[mt][3] : qc0[mt][3];
                float e00 = nat_e(s00, wr0, wc0, ct0, rowar[0][mt], rowjc[0][mt], rowbias[0][mt], rs);
                float e01 = nat_e(s01, wr1, wc1, ct1, rowar[0][mt], rowjc[0][mt], rowbias[0][mt], rs);
                float e10 = nat_e(s10, wr0, wc0, ct0, rowar[1][mt], rowjc[1][mt], rowbias[1][mt], rs);
                float e11 = nat_e(s11, wr1, wc1, ct1, rowar[1][mt], rowjc[1][mt], rowbias[1][mt], rs);
                *(half2*)(smraw + SM_P + r0 * 432 + c0 * 2)       = __floats2half2_rn(e00, e01);
                *(half2*)(smraw + SM_P + (r0 + 8) * 432 + c0 * 2) = __floats2half2_rn(e10, e11);
            }
        }
    }

    cp_wait0();
    __syncthreads();

    // ---- AV phase: O[64x40] = P[64x208] @ V[208x40] (B via ldmatrix.trans) ----
    const int  mtav    = w & 3;
    const bool hi_half = (w >= 4);
    float av[3][4];
#pragma unroll
    for (int u2 = 0; u2 < 3; u2++)
#pragma unroll
        for (int e = 0; e < 4; e++) av[u2][e] = 0.0f;

    const unsigned pa = sm0 + SM_P +
        (mtav * 16 + (lane & 15)) * 432 + (lane >> 4) * 16;
    const unsigned pb = sm0 + SM_V + (lane & 15) * 80 +
        (hi_half ? 32u : 0u) + (lane >> 4) * 16;
    const unsigned pb2 = sm0 + SM_V + (lane & 15) * 80 + 64 + (lane >> 4) * 16;

#pragma unroll
    for (int ks = 0; ks < 13; ks++) {
        uint32_t a4[4], b4[4];
        ldmx4(a4[0], a4[1], a4[2], a4[3], pa + ks * 32);
        ldmx4t(b4[0], b4[1], b4[2], b4[3], pb + ks * 1280);
        mma16816(av[0][0], av[0][1], av[0][2], av[0][3],
                 a4[0], a4[1], a4[2], a4[3], b4[0], b4[1]);
        mma16816(av[1][0], av[1][1], av[1][2], av[1][3],
                 a4[0], a4[1], a4[2], a4[3], b4[2], b4[3]);
        if (hi_half) {
            uint32_t b2[4];
            ldmx4t(b2[0], b2[1], b2[2], b2[3], pb2 + ks * 1280);
            mma16816(av[2][0], av[2][1], av[2][2], av[2][3],
                     a4[0], a4[1], a4[2], a4[3], b2[0], b2[1]);
        }
    }

    if (hi_half && (lane & 3) == 0) {
        const int r0 = mtav * 16 + (lane >> 2);
        *(float*)(smraw + SM_ZS + r0 * 4)       = av[2][0];
        *(float*)(smraw + SM_ZS + (r0 + 8) * 4) = av[2][2];
    }
    __syncthreads();

    // ---- normalize + store fp16 ----
    {
        const int r0 = mtav * 16 + (lane >> 2);
        const float zi0 = __frcp_rn(*(float*)(smraw + SM_ZS + r0 * 4));
        const float zi1 = __frcp_rn(*(float*)(smraw + SM_ZS + (r0 + 8) * 4));
        const int pix0 = (bb * HH + i0 + (r0 >> 3)) * WW + j0 + (r0 & 7);
        const int pix1 = (bb * HH + i0 + (r0 >> 3) + 1) * WW + j0 + (r0 & 7);
#pragma unroll
        for (int nti = 0; nti < 2; nti++) {
            const int d0 = (hi_half ? 16 : 0) + nti * 8 + (lane & 3) * 2;
            *(half2*)&g_att1[(size_t)pix0 * CC + h * 32 + d0] =
                __floats2half2_rn(av[nti][0] * zi0, av[nti][1] * zi0);
            *(half2*)&g_att1[(size_t)pix1 * CC + h * 32 + d0] =
                __floats2half2_rn(av[nti][2] * zi1, av[nti][3] * zi1);
        }
    }
}

// ---------------------------------------------------------------------------
// Launch
// ---------------------------------------------------------------------------
extern "C" void kernel_launch(void* const* d_in, const int* in_sizes, int n_in,
                              void* d_out, int out_size)
{
    const float* x       = (const float*)d_in[0];
    const float* q_extra = (const float*)d_in[1];
    const float* kv_w    = (const float*)d_in[2];
    const float* kv_b    = (const float*)d_in[3];
    const float* rpb     = (const float*)d_in[4];
    const float* proj_w  = (const float*)d_in[5];
    const float* proj_b  = (const float*)d_in[6];
    float* out = (float*)d_out;

    h16 *kv_ptr = nullptr, *x1_ptr = nullptr, *att1_ptr = nullptr;
    h16 *w1_ptr = nullptr, *pw1_ptr = nullptr;
    cudaGetSymbolAddress((void**)&kv_ptr,   g_kv);
    cudaGetSymbolAddress((void**)&x1_ptr,   g_x1);
    cudaGetSymbolAddress((void**)&att1_ptr, g_att1);
    cudaGetSymbolAddress((void**)&w1_ptr,   g_w1);
    cudaGetSymbolAddress((void**)&pw1_ptr,  g_pw1);

    const int smem128 = 4 * (128 + 128) * 80;   // 81920
    const int smem64  = 4 * (128 + 64)  * 80;   // 61440
    cudaFuncSetAttribute(gemm_f16<128, 1>,
                         cudaFuncAttributeMaxDynamicSharedMemorySize, smem128);
    cudaFuncSetAttribute(gemm_f16<64, 0>,
                         cudaFuncAttributeMaxDynamicSharedMemorySize, smem64);
    cudaFuncSetAttribute(natt_mma_kernel,
                         cudaFuncAttributeMaxDynamicSharedMemorySize, NATT_SMEM);

    // 0) convert fp32 -> fp16 (x, kv_w, proj_w)
    conv_all_kernel<<<(NSPLIT / 2 + 255) / 256, 256>>>(
        x, kv_w, proj_w, x1_ptr, w1_ptr, pw1_ptr);

    // 1) kv = x @ kv_w^T + kv_b   (fp16 output, K=256)
    gemm_f16<128, 1><<<dim3(KV_N / 128, NPIX / 128), 256, smem128>>>(
        x1_ptr, w1_ptr, kv_b, kv_ptr, NPIX, KV_N);

    // 2) tensor-core neighborhood attention: 8x8 tiles -> grid (49, 8, 2)
    natt_mma_kernel<<<dim3(49, HEADS, BB), 256, NATT_SMEM>>>(q_extra, rpb);

    // 3) out = att @ proj_w^T + proj_b   (fp32 output, K=256)
    gemm_f16<64, 0><<<dim3(CC / 64, NPIX / 128), 256, smem64>>>(
        att1_ptr, pw1_ptr, proj_b, out, NPIX, CC);
}